// round 5
// baseline (speedup 1.0000x reference)
#include <cuda_runtime.h>
#include <cuda_bf16.h>
#include <cstdint>
#include <cstddef>

// Problem constants
#define L_SEQ  2048
#define BATCH  32
#define DIM    512
#define NLAY   4
#define MTOT   (L_SEQ*BATCH)   // 65536
#define NTOT   (3*DIM)         // 1536

// ---------------- device-global scratch (sanctioned no-alloc path) ---------
__device__ __nv_bfloat16 g_h_hi[(size_t)MTOT*DIM];       // 64 MB
__device__ __nv_bfloat16 g_h_lo[(size_t)MTOT*DIM];       // 64 MB
__device__ __nv_bfloat16 g_W_hi[(size_t)NLAY*NTOT*DIM];  // 6 MB  [l][n][k]
__device__ __nv_bfloat16 g_W_lo[(size_t)NLAY*NTOT*DIM];  // 6 MB
__device__ float         g_U[(size_t)MTOT*NTOT];         // 384 MB [m][n]

// ---------------- helpers ---------------------------------------------------
__device__ __forceinline__ uint32_t smem_u32(const void* p) {
    uint32_t a;
    asm("{ .reg .u64 t; cvta.to.shared.u64 t, %1; cvt.u32.u64 %0, t; }"
        : "=r"(a) : "l"(p));
    return a;
}
__device__ __forceinline__ void cp16(uint32_t dst, const void* src) {
    asm volatile("cp.async.cg.shared.global [%0], [%1], 16;\n"
                 :: "r"(dst), "l"(src));
}
#define CP_COMMIT() asm volatile("cp.async.commit_group;")

__device__ __forceinline__ void ldsm4(uint32_t* r, uint32_t addr) {
    asm volatile("ldmatrix.sync.aligned.m8n8.x4.shared.b16 {%0,%1,%2,%3}, [%4];"
                 : "=r"(r[0]), "=r"(r[1]), "=r"(r[2]), "=r"(r[3]) : "r"(addr));
}
__device__ __forceinline__ void mma16816(float* d, const uint32_t* a, const uint32_t* b) {
    asm volatile("mma.sync.aligned.m16n8k16.row.col.f32.bf16.bf16.f32 "
                 "{%0,%1,%2,%3}, {%4,%5,%6,%7}, {%8,%9}, {%0,%1,%2,%3};"
                 : "+f"(d[0]), "+f"(d[1]), "+f"(d[2]), "+f"(d[3])
                 : "r"(a[0]), "r"(a[1]), "r"(a[2]), "r"(a[3]),
                   "r"(b[0]), "r"(b[1]));
}

// ---------------- GEMM config ----------------------------------------------
// CTA tile 128x128, BK=64 (128B rows), 3-stage cp.async pipeline,
// bf16x3 compensated passes accumulated into the same fp32 accumulators.
#define MT 128
#define NT 128
#define KC 64
#define NCHUNK (DIM/KC)                   // 8
#define OFF_AH 0
#define OFF_AL 16384
#define OFF_BH 32768
#define OFF_BL 49152
#define STAGE_BYTES 65536
#define NSTAGE 3
#define SMEM_TOTAL (NSTAGE*STAGE_BYTES)   // 196608

// swizzled byte offset inside a 128x128B tile
__device__ __forceinline__ uint32_t swz(uint32_t row, uint32_t chunk) {
    return row * 128u + (((chunk ^ (row & 7u)) & 7u) << 4);
}

// load one 128x64 bf16 tile (cp.async), swizzled
__device__ __forceinline__ void load_tile(uint32_t dst_base,
                                          const __nv_bfloat16* __restrict__ src,
                                          int kc, int tid)
{
    #pragma unroll
    for (int i = 0; i < 4; i++) {
        int o = tid + (i << 8);
        uint32_t r = (uint32_t)(o >> 3), c = (uint32_t)(o & 7);
        cp16(dst_base + swz(r, c), src + (size_t)r * DIM + kc + (c << 3));
    }
}
__device__ __forceinline__ void load_stage(uint32_t st, int kc, int tid,
    const __nv_bfloat16* __restrict__ ah, const __nv_bfloat16* __restrict__ al,
    const __nv_bfloat16* __restrict__ bh, const __nv_bfloat16* __restrict__ bl)
{
    load_tile(st + OFF_AH, ah, kc, tid);
    load_tile(st + OFF_AL, al, kc, tid);
    load_tile(st + OFF_BH, bh, kc, tid);
    load_tile(st + OFF_BL, bl, kc, tid);
    CP_COMMIT();
}

__global__ void __launch_bounds__(256, 1)
gemm_kernel(int layer, int n_tiles)
{
    extern __shared__ __align__(1024) char smem[];
    uint32_t sb = smem_u32(smem);
    int tid  = threadIdx.x;
    int wid  = tid >> 5, lane = tid & 31;
    int wm   = wid & 3;         // 4 warps along M (32 rows each)
    int wn   = wid >> 2;        // 2 warps along N (64 cols each)
    int m0   = (blockIdx.x / n_tiles) * MT;
    int n0   = (blockIdx.x % n_tiles) * NT;

    const __nv_bfloat16* ah = g_h_hi + (size_t)m0 * DIM;
    const __nv_bfloat16* al = g_h_lo + (size_t)m0 * DIM;
    const __nv_bfloat16* bh = g_W_hi + ((size_t)layer * NTOT + n0) * DIM;
    const __nv_bfloat16* bl = g_W_lo + ((size_t)layer * NTOT + n0) * DIM;

    // ldmatrix per-lane geometry
    int t  = lane >> 3;              // which 8x8 within .x4
    int lr = lane & 7;               // row within 8x8
    uint32_t rA0 = (uint32_t)(wm * 32 + ((t & 1) << 3) + lr);
    uint32_t rB0 = (uint32_t)(wn * 64 + ((t & 1) << 3) + lr);
    uint32_t chi = (uint32_t)(t >> 1);

    float acc[2][8][4];
    #pragma unroll
    for (int i = 0; i < 2; i++)
        #pragma unroll
        for (int j = 0; j < 8; j++)
            #pragma unroll
            for (int q = 0; q < 4; q++) acc[i][j][q] = 0.f;

    // prologue: chunks 0,1 into stages 0,1
    load_stage(sb,                0,  tid, ah, al, bh, bl);
    load_stage(sb + STAGE_BYTES,  KC, tid, ah, al, bh, bl);

    for (int chunk = 0; chunk < NCHUNK; ++chunk) {
        if (chunk < NCHUNK - 1) asm volatile("cp.async.wait_group 1;" ::: "memory");
        else                    asm volatile("cp.async.wait_group 0;" ::: "memory");
        __syncthreads();

        // issue loads for chunk+2 into stage (chunk+2)%3 (safe: all warps done
        // with that stage as of the barrier above), overlapping with compute
        if (chunk + 2 < NCHUNK)
            load_stage(sb + (uint32_t)((chunk + 2) % NSTAGE) * STAGE_BYTES,
                       (chunk + 2) * KC, tid, ah, al, bh, bl);

        uint32_t st = sb + (uint32_t)(chunk % NSTAGE) * STAGE_BYTES;
        #pragma unroll
        for (int ks = 0; ks < 4; ks++) {
            uint32_t cc = 2u * ks + chi;
            uint32_t aH[2][4], aL[2][4], bH[8][2], bL[8][2];
            #pragma unroll
            for (int mt = 0; mt < 2; mt++) {
                uint32_t rr = rA0 + (uint32_t)(mt << 4);
                uint32_t off = swz(rr, cc);
                ldsm4(aH[mt], st + OFF_AH + off);
                ldsm4(aL[mt], st + OFF_AL + off);
            }
            #pragma unroll
            for (int bt = 0; bt < 4; bt++) {
                uint32_t rr = rB0 + (uint32_t)(bt << 4);
                uint32_t off = swz(rr, cc);
                uint32_t r4[4];
                ldsm4(r4, st + OFF_BH + off);
                bH[2*bt][0] = r4[0]; bH[2*bt][1] = r4[2];
                bH[2*bt+1][0] = r4[1]; bH[2*bt+1][1] = r4[3];
                ldsm4(r4, st + OFF_BL + off);
                bL[2*bt][0] = r4[0]; bL[2*bt][1] = r4[2];
                bL[2*bt+1][0] = r4[1]; bL[2*bt+1][1] = r4[3];
            }
            #pragma unroll
            for (int mt = 0; mt < 2; mt++)
                #pragma unroll
                for (int nt = 0; nt < 8; nt++) {
                    mma16816(acc[mt][nt], aH[mt], bH[nt]);
                    mma16816(acc[mt][nt], aH[mt], bL[nt]);
                    mma16816(acc[mt][nt], aL[mt], bH[nt]);
                }
        }
    }

    // epilogue: write U
    int rbase = lane >> 2;
    int cbase = (lane & 3) * 2;
    #pragma unroll
    for (int mt = 0; mt < 2; mt++) {
        int mrow = m0 + wm * 32 + mt * 16 + rbase;
        #pragma unroll
        for (int nt = 0; nt < 8; nt++) {
            int ncol = n0 + wn * 64 + nt * 8 + cbase;
            float2 v0 = make_float2(acc[mt][nt][0], acc[mt][nt][1]);
            float2 v1 = make_float2(acc[mt][nt][2], acc[mt][nt][3]);
            *(float2*)(g_U + (size_t)mrow * NTOT + ncol)       = v0;
            *(float2*)(g_U + (size_t)(mrow + 8) * NTOT + ncol) = v1;
        }
    }
}

// ---------------- pre-pass: split/transpose inputs --------------------------
// x[b][t][d] fp32 -> g_h_{hi,lo}[(t*B+b)][d] bf16x2 split
__global__ void __launch_bounds__(128)
split_x_kernel(const float* __restrict__ x)
{
    int e = blockIdx.x;                  // e = b*L + t
    int b = e >> 11, tt = e & (L_SEQ - 1);
    const float4* src = (const float4*)(x + (size_t)e * DIM);
    size_t drow = (size_t)(tt * BATCH + b) * DIM;
    int i = threadIdx.x;
    float4 v = src[i];
    __nv_bfloat16 h0 = __float2bfloat16(v.x), h1 = __float2bfloat16(v.y);
    __nv_bfloat16 h2 = __float2bfloat16(v.z), h3 = __float2bfloat16(v.w);
    __nv_bfloat16 l0 = __float2bfloat16(v.x - __bfloat162float(h0));
    __nv_bfloat16 l1 = __float2bfloat16(v.y - __bfloat162float(h1));
    __nv_bfloat16 l2 = __float2bfloat16(v.z - __bfloat162float(h2));
    __nv_bfloat16 l3 = __float2bfloat16(v.w - __bfloat162float(h3));
    union { __nv_bfloat16 h[4]; uint2 u; } ph, pl;
    ph.h[0] = h0; ph.h[1] = h1; ph.h[2] = h2; ph.h[3] = h3;
    pl.h[0] = l0; pl.h[1] = l1; pl.h[2] = l2; pl.h[3] = l3;
    *(uint2*)(g_h_hi + drow + 4 * i) = ph.u;
    *(uint2*)(g_h_lo + drow + 4 * i) = pl.u;
}

// W[l][k][n] fp32 -> g_W_{hi,lo}[l][n][k] bf16x2 split
__global__ void __launch_bounds__(256)
split_w_kernel(const float* __restrict__ W)
{
    int o = blockIdx.x * 256 + threadIdx.x;           // [l][n][k] linear
    int l = o / (NTOT * DIM);
    int rem = o - l * (NTOT * DIM);
    int n = rem >> 9, k = rem & (DIM - 1);
    float w = W[(size_t)l * DIM * NTOT + (size_t)k * NTOT + n];
    __nv_bfloat16 hi = __float2bfloat16(w);
    g_W_hi[o] = hi;
    g_W_lo[o] = __float2bfloat16(w - __bfloat162float(hi));
}

// ---------------- recurrence -------------------------------------------------
// one thread per (b,d) chain; blocked double-buffered register prefetch.
#define RB 16
#define NBLK (L_SEQ/RB)    // 128

template<bool LAST>
struct RecurBuf {
    float u0[RB], u1[RB], u2[RB], xv[RB];
    int   mk[RB];
};

template<bool LAST>
__device__ __forceinline__ void recur_load_block(
    RecurBuf<LAST>& bb, int t0,
    const float* __restrict__ u,
    const __nv_bfloat16* __restrict__ hh, const __nv_bfloat16* __restrict__ hl,
    const int* __restrict__ mk)
{
    const size_t SU = (size_t)BATCH * NTOT;
    const size_t SH = (size_t)BATCH * DIM;
    #pragma unroll
    for (int j = 0; j < RB; j++) {
        const float* up = u + (size_t)(t0 + j) * SU;
        bb.u0[j] = up[0];
        bb.u1[j] = up[DIM];
        if (!LAST) {
            bb.u2[j] = up[2 * DIM];
            bb.xv[j] = __bfloat162float(hh[(size_t)(t0 + j) * SH]) +
                       __bfloat162float(hl[(size_t)(t0 + j) * SH]);
        }
        bb.mk[j] = mk[t0 + j];
    }
}

template<bool LAST>
__device__ __forceinline__ void recur_compute_block(
    RecurBuf<LAST>& bb, int t0, float& c,
    float vf, float vr, float bf, float br,
    __nv_bfloat16* __restrict__ hh, __nv_bfloat16* __restrict__ hl)
{
    const size_t SH = (size_t)BATCH * DIM;
    #pragma unroll
    for (int j = 0; j < RB; j++) {
        bool pad = (bb.mk[j] == 0);
        float z = fmaf(vf, c, bb.u1[j] + bf);
        float f = __fdividef(1.f, 1.f + __expf(-z));
        float cn = fmaf(f, c - bb.u0[j], bb.u0[j]);
        c = pad ? c : cn;
        if (!LAST) {
            float xv = bb.xv[j];
            float z2 = fmaf(vr, c, bb.u2[j] + br);
            float r  = __fdividef(1.f, 1.f + __expf(-z2));
            float ht = pad ? 0.f : fmaf(r, c - xv, xv);
            __nv_bfloat16 hi = __float2bfloat16(ht);
            hh[(size_t)(t0 + j) * SH] = hi;
            hl[(size_t)(t0 + j) * SH] = __float2bfloat16(ht - __bfloat162float(hi));
        }
    }
}

template<bool LAST>
__global__ void __launch_bounds__(128)
recur_kernel(const float* __restrict__ state, const float* __restrict__ vc,
             const float* __restrict__ bias, const int* __restrict__ mask,
             float* __restrict__ out, int layer)
{
    int g = blockIdx.x * 128 + threadIdx.x;           // 0..16383
    int b = g >> 9, d = g & (DIM - 1);
    float vf = vc[layer * 2 * DIM + d];
    float vr = LAST ? 0.f : vc[layer * 2 * DIM + DIM + d];
    float bf = bias[layer * 2 * DIM + d];
    float br = LAST ? 0.f : bias[layer * 2 * DIM + DIM + d];
    float c  = state[layer * DIM + d];

    const float* u = g_U + (size_t)b * NTOT + d;
    __nv_bfloat16* hh = g_h_hi + (size_t)b * DIM + d;
    __nv_bfloat16* hl = g_h_lo + (size_t)b * DIM + d;
    const int* mk = mask + b * L_SEQ;

    RecurBuf<LAST> buf0, buf1;
    recur_load_block<LAST>(buf0, 0, u, hh, hl, mk);

    // explicit 2-block unroll so all buffer indices are compile-time constants
    for (int blk = 0; blk < NBLK; blk += 2) {
        recur_load_block<LAST>(buf1, (blk + 1) * RB, u, hh, hl, mk);
        recur_compute_block<LAST>(buf0, blk * RB, c, vf, vr, bf, br, hh, hl);
        if (blk + 2 < NBLK)
            recur_load_block<LAST>(buf0, (blk + 2) * RB, u, hh, hl, mk);
        recur_compute_block<LAST>(buf1, (blk + 1) * RB, c, vf, vr, bf, br, hh, hl);
    }

    if (layer == 0) out[g] = c;
    else            out[g] += c;
}

// ---------------- launch -----------------------------------------------------
extern "C" void kernel_launch(void* const* d_in, const int* in_sizes, int n_in,
                              void* d_out, int out_size)
{
    const float* x     = (const float*)d_in[0];
    const int*   mask  = (const int*)  d_in[1];
    const float* state = (const float*)d_in[2];
    const float* W     = (const float*)d_in[3];
    const float* vc    = (const float*)d_in[4];
    const float* bias  = (const float*)d_in[5];
    float* out = (float*)d_out;

    cudaFuncSetAttribute(gemm_kernel,
                         cudaFuncAttributeMaxDynamicSharedMemorySize, SMEM_TOTAL);

    split_x_kernel<<<BATCH * L_SEQ, 128>>>(x);
    split_w_kernel<<<(NLAY * NTOT * DIM) / 256, 256>>>(W);

    for (int l = 0; l < NLAY; l++) {
        int nt = (l == NLAY - 1) ? 8 : 12;   // last layer: skip u2 tiles
        gemm_kernel<<<(MTOT / MT) * nt, 256, SMEM_TOTAL>>>(l, nt);
        if (l == NLAY - 1)
            recur_kernel<true><<<(BATCH * DIM) / 128, 128>>>(state, vc, bias, mask, out, l);
        else
            recur_kernel<false><<<(BATCH * DIM) / 128, 128>>>(state, vc, bias, mask, out, l);
    }
    (void)in_sizes; (void)n_in; (void)out_size;
}

// round 6
// speedup vs baseline: 1.0783x; 1.0783x over previous
#include <cuda_runtime.h>
#include <cuda_bf16.h>
#include <cstdint>
#include <cstddef>

// Problem constants
#define L_SEQ  2048
#define BATCH  32
#define DIM    512
#define NLAY   4
#define MTOT   (L_SEQ*BATCH)   // 65536
#define NTOT   (3*DIM)         // 1536
#define PS     ((size_t)MTOT*DIM)       // floats per U plane
#define TSTRIDE 16384                   // elements per t-step in a plane (32*512)

// ---------------- device-global scratch (sanctioned no-alloc path) ---------
__device__ __nv_bfloat16 g_h_hi[(size_t)MTOT*DIM];       // 64 MB
__device__ __nv_bfloat16 g_h_lo[(size_t)MTOT*DIM];       // 64 MB
__device__ __nv_bfloat16 g_W_hi[(size_t)NLAY*NTOT*DIM];  // 6 MB  [l][n][k]
__device__ __nv_bfloat16 g_W_lo[(size_t)NLAY*NTOT*DIM];  // 6 MB
__device__ float         g_U[(size_t)MTOT*NTOT];         // 384 MB: 3 planes [p][m][512]
__device__ uint32_t      g_mb[BATCH*(L_SEQ/32)];         // packed mask bits

// ---------------- helpers ---------------------------------------------------
__device__ __forceinline__ uint32_t smem_u32(const void* p) {
    uint32_t a;
    asm("{ .reg .u64 t; cvta.to.shared.u64 t, %1; cvt.u32.u64 %0, t; }"
        : "=r"(a) : "l"(p));
    return a;
}
__device__ __forceinline__ void cp16(uint32_t dst, const void* src) {
    asm volatile("cp.async.cg.shared.global [%0], [%1], 16;\n"
                 :: "r"(dst), "l"(src));
}
__device__ __forceinline__ void cp4(uint32_t dst, const void* src) {
    asm volatile("cp.async.ca.shared.global [%0], [%1], 4;\n"
                 :: "r"(dst), "l"(src));
}
#define CP_COMMIT() asm volatile("cp.async.commit_group;")
#define CP_WAIT(n)  asm volatile("cp.async.wait_group %0;" :: "n"(n) : "memory")

__device__ __forceinline__ void ldsm4(uint32_t* r, uint32_t addr) {
    asm volatile("ldmatrix.sync.aligned.m8n8.x4.shared.b16 {%0,%1,%2,%3}, [%4];"
                 : "=r"(r[0]), "=r"(r[1]), "=r"(r[2]), "=r"(r[3]) : "r"(addr));
}
__device__ __forceinline__ void mma16816(float* d, const uint32_t* a, const uint32_t* b) {
    asm volatile("mma.sync.aligned.m16n8k16.row.col.f32.bf16.bf16.f32 "
                 "{%0,%1,%2,%3}, {%4,%5,%6,%7}, {%8,%9}, {%0,%1,%2,%3};"
                 : "+f"(d[0]), "+f"(d[1]), "+f"(d[2]), "+f"(d[3])
                 : "r"(a[0]), "r"(a[1]), "r"(a[2]), "r"(a[3]),
                   "r"(b[0]), "r"(b[1]));
}

// ---------------- GEMM config ----------------------------------------------
#define MT 128
#define NT 128
#define KC 64
#define NCHUNK (DIM/KC)                   // 8
#define OFF_AH 0
#define OFF_AL 16384
#define OFF_BH 32768
#define OFF_BL 49152
#define STAGE_BYTES 65536
#define NSTAGE 3
#define SMEM_TOTAL (NSTAGE*STAGE_BYTES)   // 196608

__device__ __forceinline__ uint32_t swz(uint32_t row, uint32_t chunk) {
    return row * 128u + (((chunk ^ (row & 7u)) & 7u) << 4);
}

__device__ __forceinline__ void load_tile(uint32_t dst_base,
                                          const __nv_bfloat16* __restrict__ src,
                                          int kc, int tid)
{
    #pragma unroll
    for (int i = 0; i < 4; i++) {
        int o = tid + (i << 8);
        uint32_t r = (uint32_t)(o >> 3), c = (uint32_t)(o & 7);
        cp16(dst_base + swz(r, c), src + (size_t)r * DIM + kc + (c << 3));
    }
}
__device__ __forceinline__ void load_stage(uint32_t st, int kc, int tid,
    const __nv_bfloat16* __restrict__ ah, const __nv_bfloat16* __restrict__ al,
    const __nv_bfloat16* __restrict__ bh, const __nv_bfloat16* __restrict__ bl)
{
    load_tile(st + OFF_AH, ah, kc, tid);
    load_tile(st + OFF_AL, al, kc, tid);
    load_tile(st + OFF_BH, bh, kc, tid);
    load_tile(st + OFF_BL, bl, kc, tid);
    CP_COMMIT();
}

struct Frag {
    uint32_t aH[2][4], aL[2][4];
    uint32_t bH[8][2], bL[8][2];
};

__device__ __forceinline__ void load_frag(Frag& f, uint32_t st, int ks,
                                          uint32_t rA0, uint32_t rB0, uint32_t chi)
{
    uint32_t cc = 2u * (uint32_t)ks + chi;
    #pragma unroll
    for (int mt = 0; mt < 2; mt++) {
        uint32_t off = swz(rA0 + (uint32_t)(mt << 4), cc);
        ldsm4(f.aH[mt], st + OFF_AH + off);
        ldsm4(f.aL[mt], st + OFF_AL + off);
    }
    #pragma unroll
    for (int bt = 0; bt < 4; bt++) {
        uint32_t off = swz(rB0 + (uint32_t)(bt << 4), cc);
        uint32_t r4[4];
        ldsm4(r4, st + OFF_BH + off);
        f.bH[2*bt][0] = r4[0];   f.bH[2*bt][1] = r4[2];
        f.bH[2*bt+1][0] = r4[1]; f.bH[2*bt+1][1] = r4[3];
        ldsm4(r4, st + OFF_BL + off);
        f.bL[2*bt][0] = r4[0];   f.bL[2*bt][1] = r4[2];
        f.bL[2*bt+1][0] = r4[1]; f.bL[2*bt+1][1] = r4[3];
    }
}
__device__ __forceinline__ void mma_all(float acc[2][8][4], const Frag& f)
{
    #pragma unroll
    for (int mt = 0; mt < 2; mt++)
        #pragma unroll
        for (int nt = 0; nt < 8; nt++) {
            mma16816(acc[mt][nt], f.aH[mt], f.bH[nt]);
            mma16816(acc[mt][nt], f.aH[mt], f.bL[nt]);
            mma16816(acc[mt][nt], f.aL[mt], f.bH[nt]);
        }
}

__global__ void __launch_bounds__(256, 1)
gemm_kernel(int layer, int n_tiles)
{
    extern __shared__ __align__(1024) char smem[];
    uint32_t sb = smem_u32(smem);
    int tid  = threadIdx.x;
    int wid  = tid >> 5, lane = tid & 31;
    int wm   = wid & 3;
    int wn   = wid >> 2;
    int m0   = (blockIdx.x / n_tiles) * MT;
    int n0   = (blockIdx.x % n_tiles) * NT;

    const __nv_bfloat16* ah = g_h_hi + (size_t)m0 * DIM;
    const __nv_bfloat16* al = g_h_lo + (size_t)m0 * DIM;
    const __nv_bfloat16* bh = g_W_hi + ((size_t)layer * NTOT + n0) * DIM;
    const __nv_bfloat16* bl = g_W_lo + ((size_t)layer * NTOT + n0) * DIM;

    int t  = lane >> 3;
    int lr = lane & 7;
    uint32_t rA0 = (uint32_t)(wm * 32 + ((t & 1) << 3) + lr);
    uint32_t rB0 = (uint32_t)(wn * 64 + ((t & 1) << 3) + lr);
    uint32_t chi = (uint32_t)(t >> 1);

    float acc[2][8][4];
    #pragma unroll
    for (int i = 0; i < 2; i++)
        #pragma unroll
        for (int j = 0; j < 8; j++)
            #pragma unroll
            for (int q = 0; q < 4; q++) acc[i][j][q] = 0.f;

    load_stage(sb,                0,  tid, ah, al, bh, bl);
    load_stage(sb + STAGE_BYTES,  KC, tid, ah, al, bh, bl);

    Frag fA, fB;
    for (int chunk = 0; chunk < NCHUNK; ++chunk) {
        if (chunk < NCHUNK - 1) CP_WAIT(1);
        else                    CP_WAIT(0);
        __syncthreads();

        uint32_t st = sb + (uint32_t)(chunk % NSTAGE) * STAGE_BYTES;

        // first fragment before the prefetch burst so MMA starts sooner
        load_frag(fA, st, 0, rA0, rB0, chi);
        if (chunk + 2 < NCHUNK)
            load_stage(sb + (uint32_t)((chunk + 2) % NSTAGE) * STAGE_BYTES,
                       (chunk + 2) * KC, tid, ah, al, bh, bl);

        load_frag(fB, st, 1, rA0, rB0, chi);  mma_all(acc, fA);
        load_frag(fA, st, 2, rA0, rB0, chi);  mma_all(acc, fB);
        load_frag(fB, st, 3, rA0, rB0, chi);  mma_all(acc, fA);
        mma_all(acc, fB);
    }

    // epilogue: write U into planar layout [plane][m][512]
    int plane = n0 >> 9;
    int nc0   = n0 & 511;
    float* Up = g_U + (size_t)plane * PS;
    int rbase = lane >> 2;
    int cbase = (lane & 3) * 2;
    #pragma unroll
    for (int mt = 0; mt < 2; mt++) {
        int mrow = m0 + wm * 32 + mt * 16 + rbase;
        #pragma unroll
        for (int nt = 0; nt < 8; nt++) {
            int ncol = nc0 + wn * 64 + nt * 8 + cbase;
            float2 v0 = make_float2(acc[mt][nt][0], acc[mt][nt][1]);
            float2 v1 = make_float2(acc[mt][nt][2], acc[mt][nt][3]);
            *(float2*)(Up + (size_t)mrow * DIM + ncol)       = v0;
            *(float2*)(Up + (size_t)(mrow + 8) * DIM + ncol) = v1;
        }
    }
}

// ---------------- pre-passes -------------------------------------------------
__global__ void __launch_bounds__(128)
split_x_kernel(const float* __restrict__ x)
{
    int e = blockIdx.x;                  // e = b*L + t
    int b = e >> 11, tt = e & (L_SEQ - 1);
    const float4* src = (const float4*)(x + (size_t)e * DIM);
    size_t drow = (size_t)(tt * BATCH + b) * DIM;
    int i = threadIdx.x;
    float4 v = src[i];
    __nv_bfloat16 h0 = __float2bfloat16(v.x), h1 = __float2bfloat16(v.y);
    __nv_bfloat16 h2 = __float2bfloat16(v.z), h3 = __float2bfloat16(v.w);
    __nv_bfloat16 l0 = __float2bfloat16(v.x - __bfloat162float(h0));
    __nv_bfloat16 l1 = __float2bfloat16(v.y - __bfloat162float(h1));
    __nv_bfloat16 l2 = __float2bfloat16(v.z - __bfloat162float(h2));
    __nv_bfloat16 l3 = __float2bfloat16(v.w - __bfloat162float(h3));
    union { __nv_bfloat16 h[4]; uint2 u; } ph, pl;
    ph.h[0] = h0; ph.h[1] = h1; ph.h[2] = h2; ph.h[3] = h3;
    pl.h[0] = l0; pl.h[1] = l1; pl.h[2] = l2; pl.h[3] = l3;
    *(uint2*)(g_h_hi + drow + 4 * i) = ph.u;
    *(uint2*)(g_h_lo + drow + 4 * i) = pl.u;
}

__global__ void __launch_bounds__(256)
split_w_kernel(const float* __restrict__ W)
{
    int o = blockIdx.x * 256 + threadIdx.x;
    int l = o / (NTOT * DIM);
    int rem = o - l * (NTOT * DIM);
    int n = rem >> 9, k = rem & (DIM - 1);
    float w = W[(size_t)l * DIM * NTOT + (size_t)k * NTOT + n];
    __nv_bfloat16 hi = __float2bfloat16(w);
    g_W_hi[o] = hi;
    g_W_lo[o] = __float2bfloat16(w - __bfloat162float(hi));
}

__global__ void __launch_bounds__(64)
pack_mask_kernel(const int* __restrict__ mask)
{
    int b = blockIdx.x, w = threadIdx.x;   // grid 32, block 64
    uint32_t bits = 0;
    #pragma unroll 8
    for (int i = 0; i < 32; i++)
        bits |= (mask[b * L_SEQ + w * 32 + i] != 0 ? 1u : 0u) << i;
    g_mb[b * (L_SEQ/32) + w] = bits;
}

// ---------------- recurrence -------------------------------------------------
// 1 thread per (b,d) chain; u streamed via cp.async -> smem, double-buffered.
#define RB 16
#define NB (L_SEQ/RB)       // 128
#define RSMEM (2*RB*3*128*4)   // 49152 bytes

template<bool LAST>
__device__ __forceinline__ void recur_issue(uint32_t sbase, int s, int t0, int tid,
    const float* __restrict__ p0, const float* __restrict__ p1,
    const float* __restrict__ p2)
{
    #pragma unroll
    for (int j = 0; j < RB; j++) {
        uint32_t dst = sbase + (uint32_t)(((s * RB + j) * 3) * 128 + tid) * 4u;
        size_t go = (size_t)(t0 + j) * TSTRIDE;
        cp4(dst,        p0 + go);
        cp4(dst + 512,  p1 + go);
        if (!LAST) cp4(dst + 1024, p2 + go);
    }
    CP_COMMIT();
}

template<bool LAST>
__device__ __forceinline__ void recur_loadx(float* xv, int t0,
    const __nv_bfloat16* __restrict__ hh, const __nv_bfloat16* __restrict__ hl)
{
    if (!LAST) {
        #pragma unroll
        for (int j = 0; j < RB; j++) {
            size_t go = (size_t)(t0 + j) * TSTRIDE;
            xv[j] = __bfloat162float(hh[go]) + __bfloat162float(hl[go]);
        }
    }
}

template<bool LAST>
__device__ __forceinline__ void recur_compute(const float* __restrict__ su,
    int s, int tid, const float* xv, int t0, uint32_t mw, float& c,
    float vf, float vr, float bf, float br,
    __nv_bfloat16* __restrict__ hh, __nv_bfloat16* __restrict__ hl)
{
    int shb = t0 & 31;
    #pragma unroll
    for (int j = 0; j < RB; j++) {
        const float* sp = su + ((s * RB + j) * 3) * 128 + tid;
        float u0 = sp[0];
        float u1 = sp[128];
        bool pad = ((mw >> (shb + j)) & 1u) == 0u;
        float z = fmaf(vf, c, u1 + bf);
        float f = __fdividef(1.f, 1.f + __expf(-z));
        float cn = fmaf(f, c - u0, u0);
        c = pad ? c : cn;
        if (!LAST) {
            float u2 = sp[256];
            float xvj = xv[j];
            float z2 = fmaf(vr, c, u2 + br);
            float r  = __fdividef(1.f, 1.f + __expf(-z2));
            float ht = pad ? 0.f : fmaf(r, c - xvj, xvj);
            __nv_bfloat16 hi = __float2bfloat16(ht);
            size_t go = (size_t)(t0 + j) * TSTRIDE;
            hh[go] = hi;
            hl[go] = __float2bfloat16(ht - __bfloat162float(hi));
        }
    }
}

template<bool LAST>
__global__ void __launch_bounds__(128)
recur_kernel(const float* __restrict__ state, const float* __restrict__ vc,
             const float* __restrict__ bias, float* __restrict__ out, int layer)
{
    extern __shared__ float su[];       // [2][RB][3][128]
    int tid = threadIdx.x;
    int g = blockIdx.x * 128 + tid;
    int b = g >> 9, d = g & (DIM - 1);
    float vf = vc[layer * 2 * DIM + d];
    float vr = LAST ? 0.f : vc[layer * 2 * DIM + DIM + d];
    float bf = bias[layer * 2 * DIM + d];
    float br = LAST ? 0.f : bias[layer * 2 * DIM + DIM + d];
    float c  = state[layer * DIM + d];

    size_t roff = (size_t)b * DIM + d;
    const float* p0 = g_U + roff;
    const float* p1 = g_U + PS + roff;
    const float* p2 = g_U + 2 * PS + roff;
    __nv_bfloat16* hh = g_h_hi + roff;
    __nv_bfloat16* hl = g_h_lo + roff;
    const uint32_t* mb = g_mb + b * (L_SEQ/32);
    uint32_t sbase = smem_u32(su);

    float xvA[RB], xvB[RB];

    recur_issue<LAST>(sbase, 0, 0, tid, p0, p1, p2);
    recur_loadx<LAST>(xvA, 0, hh, hl);
    uint32_t mw = mb[0];

    for (int blk = 0; blk < NB; blk += 2) {
        int t0 = blk * RB;
        recur_issue<LAST>(sbase, 1, t0 + RB, tid, p0, p1, p2);
        recur_loadx<LAST>(xvB, t0 + RB, hh, hl);
        int nw = (blk >> 1) + 1;
        uint32_t mwn = mb[nw < (L_SEQ/32) ? nw : (L_SEQ/32) - 1];

        CP_WAIT(1);
        recur_compute<LAST>(su, 0, tid, xvA, t0, mw, c, vf, vr, bf, br, hh, hl);

        if (blk + 2 < NB) {
            recur_issue<LAST>(sbase, 0, t0 + 2 * RB, tid, p0, p1, p2);
            recur_loadx<LAST>(xvA, t0 + 2 * RB, hh, hl);
            CP_WAIT(1);
        } else {
            CP_WAIT(0);
        }
        recur_compute<LAST>(su, 1, tid, xvB, t0 + RB, mw, c, vf, vr, bf, br, hh, hl);
        mw = mwn;
    }

    if (layer == 0) out[g] = c;
    else            out[g] += c;
}

// ---------------- launch -----------------------------------------------------
extern "C" void kernel_launch(void* const* d_in, const int* in_sizes, int n_in,
                              void* d_out, int out_size)
{
    const float* x     = (const float*)d_in[0];
    const int*   mask  = (const int*)  d_in[1];
    const float* state = (const float*)d_in[2];
    const float* W     = (const float*)d_in[3];
    const float* vc    = (const float*)d_in[4];
    const float* bias  = (const float*)d_in[5];
    float* out = (float*)d_out;

    cudaFuncSetAttribute(gemm_kernel,
                         cudaFuncAttributeMaxDynamicSharedMemorySize, SMEM_TOTAL);
    cudaFuncSetAttribute(recur_kernel<false>,
                         cudaFuncAttributeMaxDynamicSharedMemorySize, RSMEM);
    cudaFuncSetAttribute(recur_kernel<true>,
                         cudaFuncAttributeMaxDynamicSharedMemorySize, RSMEM);

    split_x_kernel<<<BATCH * L_SEQ, 128>>>(x);
    split_w_kernel<<<(NLAY * NTOT * DIM) / 256, 256>>>(W);
    pack_mask_kernel<<<BATCH, 64>>>(mask);

    for (int l = 0; l < NLAY; l++) {
        int nt = (l == NLAY - 1) ? 8 : 12;   // last layer: skip u2 tiles
        gemm_kernel<<<(MTOT / MT) * nt, 256, SMEM_TOTAL>>>(l, nt);
        if (l == NLAY - 1)
            recur_kernel<true><<<(BATCH * DIM) / 128, 128, RSMEM>>>(state, vc, bias, out, l);
        else
            recur_kernel<false><<<(BATCH * DIM) / 128, 128, RSMEM>>>(state, vc, bias, out, l);
    }
    (void)in_sizes; (void)n_in; (void)out_size;
}

// round 8
// speedup vs baseline: 1.5762x; 1.4618x over previous
#include <cuda_runtime.h>
#include <cuda_bf16.h>
#include <cstdint>
#include <cstddef>

// Problem constants
#define L_SEQ  2048
#define BATCH  32
#define DIM    512
#define NLAY   4
#define MTOT   (L_SEQ*BATCH)   // 65536
#define NTOT   (3*DIM)         // 1536
#define PS     ((size_t)MTOT*DIM)       // floats per U plane
#define TSTRIDE 16384                   // floats per t-step (32*512)

// ---------------- device-global scratch ------------------------------------
// g_hf: A operand / h state, fp32 (tf32-rounded), mma-fragment order:
//   [m16_block][k8_block(64)][128 elems]
__device__ float g_hf[(size_t)MTOT*DIM];                 // 128 MB
// g_Wf: B operand, fragment order per layer: [l][n8_block(192)][k8_block(64)][64]
__device__ float g_Wf[(size_t)NLAY*NTOT*DIM];            // 12.6 MB
__device__ float g_U[(size_t)MTOT*NTOT];                 // 384 MB: 3 planes [p][m][512]
__device__ uint32_t g_mb[BATCH*(L_SEQ/32)];              // packed mask bits

// ---------------- helpers ---------------------------------------------------
__device__ __forceinline__ uint32_t smem_u32(const void* p) {
    uint32_t a;
    asm("{ .reg .u64 t; cvta.to.shared.u64 t, %1; cvt.u32.u64 %0, t; }"
        : "=r"(a) : "l"(p));
    return a;
}
__device__ __forceinline__ void cp16(uint32_t dst, const void* src) {
    asm volatile("cp.async.cg.shared.global [%0], [%1], 16;\n"
                 :: "r"(dst), "l"(src));
}
__device__ __forceinline__ void cp4(uint32_t dst, const void* src) {
    asm volatile("cp.async.ca.shared.global [%0], [%1], 4;\n"
                 :: "r"(dst), "l"(src));
}
#define CP_COMMIT() asm volatile("cp.async.commit_group;")
#define CP_WAIT(n)  asm volatile("cp.async.wait_group %0;" :: "n"(n) : "memory")

__device__ __forceinline__ uint32_t tf32r(float v) {
    uint32_t u;
    asm("cvt.rna.tf32.f32 %0, %1;" : "=r"(u) : "f"(v));
    return u;
}
__device__ __forceinline__ void lds128(uint32_t* r, uint32_t a) {
    asm volatile("ld.shared.v4.b32 {%0,%1,%2,%3}, [%4];"
                 : "=r"(r[0]), "=r"(r[1]), "=r"(r[2]), "=r"(r[3]) : "r"(a));
}
__device__ __forceinline__ void lds64(uint32_t* r, uint32_t a) {
    asm volatile("ld.shared.v2.b32 {%0,%1}, [%2];"
                 : "=r"(r[0]), "=r"(r[1]) : "r"(a));
}
__device__ __forceinline__ void mma_tf32(float* d, const uint32_t* a, const uint32_t* b) {
    asm volatile("mma.sync.aligned.m16n8k8.row.col.f32.tf32.tf32.f32 "
                 "{%0,%1,%2,%3}, {%4,%5,%6,%7}, {%8,%9}, {%0,%1,%2,%3};"
                 : "+f"(d[0]), "+f"(d[1]), "+f"(d[2]), "+f"(d[3])
                 : "r"(a[0]), "r"(a[1]), "r"(a[2]), "r"(a[3]),
                   "r"(b[0]), "r"(b[1]));
}

// fragment-order addressing
__device__ __forceinline__ size_t fragA(int m, int k) {
    return ((size_t)(m >> 4) * 64 + (k >> 3)) * 128 +
           (size_t)((((m & 7) * 4 + (k & 3)) * 4) + ((m >> 3) & 1) + 2 * ((k >> 2) & 1));
}
__device__ __forceinline__ size_t fragB(int n, int k) {
    return ((size_t)(n >> 3) * 64 + (k >> 3)) * 64 +
           (size_t)((((n & 7) * 4 + (k & 3)) * 2) + ((k >> 2) & 1));
}

// ---------------- GEMM config ----------------------------------------------
// CTA tile 128x64, K-chunk 64, 2-stage pipeline, 2 CTAs/SM target.
#define MT 128
#define NT 64
#define KC 64
#define NCHUNK (DIM/KC)      // 8
#define OFF_B  32768         // A: 32 KB, B: 16 KB
#define STAGE  49152
#define SMEM_TOTAL (2*STAGE) // 98304

__device__ __forceinline__ void load_stage(uint32_t st, int mb0, int nb0, int kb0,
                                           const float* __restrict__ A,
                                           const float* __restrict__ B, int tid)
{
    #pragma unroll
    for (int it = 0; it < 8; it++) {       // A: 2048 x 16B
        int i = tid + it * 256;
        int mbl = i >> 8, kbl = (i >> 5) & 7, cc = i & 31;
        const float* src = A + ((size_t)(mb0 + mbl) * 64 + (kb0 + kbl)) * 128 + cc * 4;
        cp16(st + (uint32_t)i * 16u, src);
    }
    #pragma unroll
    for (int it = 0; it < 4; it++) {       // B: 1024 x 16B
        int i = tid + it * 256;
        int nbl = i >> 7, kbl = (i >> 4) & 7, cc = i & 15;
        const float* src = B + ((size_t)(nb0 + nbl) * 64 + (kb0 + kbl)) * 64 + cc * 4;
        cp16(st + OFF_B + (uint32_t)i * 16u, src);
    }
    CP_COMMIT();
}

struct FragT { uint32_t a[2][4]; uint32_t b[4][2]; };

__device__ __forceinline__ void load_frag(FragT& f, uint32_t st, int kb,
                                          int wm, int wn, int lane)
{
    #pragma unroll
    for (int mt = 0; mt < 2; mt++)
        lds128(f.a[mt], st + (uint32_t)((((wm * 2 + mt) * 8 + kb) * 128 + lane * 4) * 4));
    #pragma unroll
    for (int nt = 0; nt < 4; nt++)
        lds64(f.b[nt], st + OFF_B +
              (uint32_t)((((wn * 4 + nt) * 8 + kb) * 64 + lane * 2) * 4));
}
__device__ __forceinline__ void mma_all(float acc[2][4][4], const FragT& f)
{
    #pragma unroll
    for (int mt = 0; mt < 2; mt++)
        #pragma unroll
        for (int nt = 0; nt < 4; nt++)
            mma_tf32(acc[mt][nt], f.a[mt], f.b[nt]);
}

__global__ void __launch_bounds__(256, 2)
gemm_kernel(int layer, int n_tiles)
{
    extern __shared__ __align__(1024) char smem[];
    uint32_t sb = smem_u32(smem);
    int tid  = threadIdx.x;
    int wid  = tid >> 5, lane = tid & 31;
    int wm   = wid & 3;          // 4 warps along M (32 rows)
    int wn   = wid >> 2;         // 2 warps along N (32 cols)
    int m0   = (blockIdx.x / n_tiles) * MT;
    int n0   = (blockIdx.x % n_tiles) * NT;
    int mb0  = m0 >> 4;
    int nb0  = n0 >> 3;

    const float* A = g_hf;
    const float* B = g_Wf + (size_t)layer * NTOT * DIM;

    float acc[2][4][4];
    #pragma unroll
    for (int i = 0; i < 2; i++)
        #pragma unroll
        for (int j = 0; j < 4; j++)
            #pragma unroll
            for (int q = 0; q < 4; q++) acc[i][j][q] = 0.f;

    load_stage(sb,         mb0, nb0, 0, A, B, tid);
    load_stage(sb + STAGE, mb0, nb0, 8, A, B, tid);

    for (int chunk = 0; chunk < NCHUNK; ++chunk) {
        if (chunk < NCHUNK - 1) CP_WAIT(1);
        else                    CP_WAIT(0);
        __syncthreads();

        uint32_t st = sb + (uint32_t)(chunk & 1) * STAGE;
        FragT f[2];
        load_frag(f[0], st, 0, wm, wn, lane);
        #pragma unroll
        for (int kb = 0; kb < 8; kb++) {
            if (kb < 7) load_frag(f[(kb + 1) & 1], st, kb + 1, wm, wn, lane);
            mma_all(acc, f[kb & 1]);
        }
        __syncthreads();

        if (chunk + 2 < NCHUNK)
            load_stage(sb + (uint32_t)(chunk & 1) * STAGE,
                       mb0, nb0, (chunk + 2) * 8, A, B, tid);
    }

    // epilogue: write U into planar layout [plane][m][512]
    int plane = n0 >> 9;
    int nc0   = n0 & 511;
    float* Up = g_U + (size_t)plane * PS;
    int rbase = lane >> 2;
    int cbase = (lane & 3) * 2;
    #pragma unroll
    for (int mt = 0; mt < 2; mt++) {
        int mrow = m0 + wm * 32 + mt * 16 + rbase;
        #pragma unroll
        for (int nt = 0; nt < 4; nt++) {
            int ncol = nc0 + wn * 32 + nt * 8 + cbase;
            *(float2*)(Up + (size_t)mrow * DIM + ncol) =
                make_float2(acc[mt][nt][0], acc[mt][nt][1]);
            *(float2*)(Up + (size_t)(mrow + 8) * DIM + ncol) =
                make_float2(acc[mt][nt][2], acc[mt][nt][3]);
        }
    }
}

// ---------------- pre-passes -------------------------------------------------
// x[b][t][d] fp32 -> g_hf fragment order (tf32-rounded), m = t*32+b
__global__ void __launch_bounds__(128)
split_x_kernel(const float* __restrict__ x)
{
    int e = blockIdx.x;                  // e = b*L + t
    int b = e >> 11, t = e & (L_SEQ - 1);
    int m = t * 32 + b;
    float4 v = ((const float4*)(x + (size_t)e * DIM))[threadIdx.x];
    int d0 = threadIdx.x * 4;
    g_hf[fragA(m, d0 + 0)] = __uint_as_float(tf32r(v.x));
    g_hf[fragA(m, d0 + 1)] = __uint_as_float(tf32r(v.y));
    g_hf[fragA(m, d0 + 2)] = __uint_as_float(tf32r(v.z));
    g_hf[fragA(m, d0 + 3)] = __uint_as_float(tf32r(v.w));
}

// W[l][k][n] fp32 -> g_Wf fragment order (tf32-rounded)
__global__ void __launch_bounds__(256)
split_w_kernel(const float* __restrict__ W)
{
    int o = blockIdx.x * 256 + threadIdx.x;   // [l][k][n] linear (coalesced read)
    int l = o / (DIM * NTOT);
    int rem = o - l * (DIM * NTOT);
    int k = rem / NTOT, n = rem - k * NTOT;
    float w = W[o];
    g_Wf[(size_t)l * NTOT * DIM + fragB(n, k)] = __uint_as_float(tf32r(w));
}

__global__ void __launch_bounds__(64)
pack_mask_kernel(const int* __restrict__ mask)
{
    int b = blockIdx.x, w = threadIdx.x;   // grid 32, block 64
    uint32_t bits = 0;
    #pragma unroll 8
    for (int i = 0; i < 32; i++)
        bits |= (mask[b * L_SEQ + w * 32 + i] != 0 ? 1u : 0u) << i;
    g_mb[b * (L_SEQ/32) + w] = bits;
}

// ---------------- recurrence -------------------------------------------------
// 1 thread per (b,d) chain; u streamed via cp.async -> smem, double-buffered.
#define RB 16
#define NB (L_SEQ/RB)          // 128
#define RSMEM (2*RB*3*128*4)   // 49152 bytes

template<bool LAST>
__device__ __forceinline__ void recur_issue(uint32_t sbase, int s, int t0, int tid,
    const float* __restrict__ p0, const float* __restrict__ p1,
    const float* __restrict__ p2)
{
    #pragma unroll
    for (int j = 0; j < RB; j++) {
        uint32_t dst = sbase + (uint32_t)(((s * RB + j) * 3) * 128 + tid) * 4u;
        size_t go = (size_t)(t0 + j) * TSTRIDE;
        cp4(dst,        p0 + go);
        cp4(dst + 512,  p1 + go);
        if (!LAST) cp4(dst + 1024, p2 + go);
    }
    CP_COMMIT();
}

template<bool LAST>
__device__ __forceinline__ void recur_loadx(float* xv, int t0,
                                            const float* __restrict__ hf)
{
    if (!LAST) {
        #pragma unroll
        for (int j = 0; j < RB; j++)
            xv[j] = hf[(size_t)(t0 + j) * TSTRIDE];
    }
}

template<bool LAST>
__device__ __forceinline__ void recur_compute(const float* __restrict__ su,
    int s, int tid, const float* xv, int t0, uint32_t mw, float& c,
    float vf, float vr, float bf, float br, float* __restrict__ hf)
{
    int shb = t0 & 31;
    #pragma unroll
    for (int j = 0; j < RB; j++) {
        const float* sp = su + ((s * RB + j) * 3) * 128 + tid;
        float u0 = sp[0];
        float u1 = sp[128];
        bool pad = ((mw >> (shb + j)) & 1u) == 0u;
        float z = fmaf(vf, c, u1 + bf);
        float f = __fdividef(1.f, 1.f + __expf(-z));
        float cn = fmaf(f, c - u0, u0);
        c = pad ? c : cn;
        if (!LAST) {
            float u2 = sp[256];
            float xvj = xv[j];
            float z2 = fmaf(vr, c, u2 + br);
            float r  = __fdividef(1.f, 1.f + __expf(-z2));
            float ht = pad ? 0.f : fmaf(r, c - xvj, xvj);
            hf[(size_t)(t0 + j) * TSTRIDE] = __uint_as_float(tf32r(ht));
        }
    }
}

template<bool LAST>
__global__ void __launch_bounds__(128)
recur_kernel(const float* __restrict__ state, const float* __restrict__ vc,
             const float* __restrict__ bias, float* __restrict__ out, int layer)
{
    extern __shared__ float su[];       // [2][RB][3][128]
    int tid = threadIdx.x;
    int g = blockIdx.x * 128 + tid;
    int b = g >> 9, d = g & (DIM - 1);
    float vf = vc[layer * 2 * DIM + d];
    float vr = LAST ? 0.f : vc[layer * 2 * DIM + DIM + d];
    float bf = bias[layer * 2 * DIM + d];
    float br = LAST ? 0.f : bias[layer * 2 * DIM + DIM + d];
    float c  = state[layer * DIM + d];

    size_t roff = (size_t)b * DIM + d;                 // U planar offset
    const float* p0 = g_U + roff;
    const float* p1 = g_U + PS + roff;
    const float* p2 = g_U + 2 * PS + roff;
    // h (x) base in fragment order, t-stride = TSTRIDE
    float* hf = g_hf + ((size_t)(b >> 4) * 64 + (d >> 3)) * 128
                + (size_t)((((b & 7) * 4 + (d & 3)) * 4) + ((b >> 3) & 1) + 2 * ((d >> 2) & 1));
    const uint32_t* mb = g_mb + b * (L_SEQ/32);
    uint32_t sbase = smem_u32(su);

    float xvA[RB], xvB[RB];

    recur_issue<LAST>(sbase, 0, 0, tid, p0, p1, p2);
    recur_loadx<LAST>(xvA, 0, hf);
    uint32_t mw = mb[0];

    for (int blk = 0; blk < NB; blk += 2) {
        int t0 = blk * RB;
        recur_issue<LAST>(sbase, 1, t0 + RB, tid, p0, p1, p2);
        recur_loadx<LAST>(xvB, t0 + RB, hf);
        int nw = (blk >> 1) + 1;
        uint32_t mwn = mb[nw < (L_SEQ/32) ? nw : (L_SEQ/32) - 1];

        CP_WAIT(1);
        recur_compute<LAST>(su, 0, tid, xvA, t0, mw, c, vf, vr, bf, br, hf);

        if (blk + 2 < NB) {
            recur_issue<LAST>(sbase, 0, t0 + 2 * RB, tid, p0, p1, p2);
            recur_loadx<LAST>(xvA, t0 + 2 * RB, hf);
            CP_WAIT(1);
        } else {
            CP_WAIT(0);
        }
        recur_compute<LAST>(su, 1, tid, xvB, t0 + RB, mw, c, vf, vr, bf, br, hf);
        mw = mwn;
    }

    if (layer == 0) out[g] = c;
    else            out[g] += c;
}

// ---------------- launch -----------------------------------------------------
extern "C" void kernel_launch(void* const* d_in, const int* in_sizes, int n_in,
                              void* d_out, int out_size)
{
    const float* x     = (const float*)d_in[0];
    const int*   mask  = (const int*)  d_in[1];
    const float* state = (const float*)d_in[2];
    const float* W     = (const float*)d_in[3];
    const float* vc    = (const float*)d_in[4];
    const float* bias  = (const float*)d_in[5];
    float* out = (float*)d_out;

    cudaFuncSetAttribute(gemm_kernel,
                         cudaFuncAttributeMaxDynamicSharedMemorySize, SMEM_TOTAL);
    cudaFuncSetAttribute(recur_kernel<false>,
                         cudaFuncAttributeMaxDynamicSharedMemorySize, RSMEM);
    cudaFuncSetAttribute(recur_kernel<true>,
                         cudaFuncAttributeMaxDynamicSharedMemorySize, RSMEM);

    split_x_kernel<<<BATCH * L_SEQ, 128>>>(x);
    split_w_kernel<<<(NLAY * NTOT * DIM) / 256, 256>>>(W);
    pack_mask_kernel<<<BATCH, 64>>>(mask);

    for (int l = 0; l < NLAY; l++) {
        int nt = (l == NLAY - 1) ? 16 : 24;   // last layer: skip u2 tiles
        gemm_kernel<<<(MTOT / MT) * nt, 256, SMEM_TOTAL>>>(l, nt);
        if (l == NLAY - 1)
            recur_kernel<true><<<(BATCH * DIM) / 128, 128, RSMEM>>>(state, vc, bias, out, l);
        else
            recur_kernel<false><<<(BATCH * DIM) / 128, 128, RSMEM>>>(state, vc, bias, out, l);
    }
    (void)in_sizes; (void)n_in; (void)out_size;
}

// round 10
// speedup vs baseline: 1.7201x; 1.0913x over previous
#include <cuda_runtime.h>
#include <cuda_bf16.h>
#include <cstdint>
#include <cstddef>

// Problem constants
#define L_SEQ  2048
#define BATCH  32
#define DIM    512
#define NLAY   4
#define MTOT   (L_SEQ*BATCH)   // 65536
#define NTOT   (3*DIM)         // 1536
#define PS     ((size_t)MTOT*DIM)       // floats per U plane
#define TSTRIDE 16384                   // floats per t-step (32*512)

// ---------------- device-global scratch ------------------------------------
// g_hf: A operand / h state, fp32 (tf32-rounded), mma-fragment order:
//   [m16_block][k8_block(64)][128 elems]
__device__ float g_hf[(size_t)MTOT*DIM];                 // 128 MB
// g_Wf: B operand, fragment order per layer: [l][n8_block(192)][k8_block(64)][64]
__device__ float g_Wf[(size_t)NLAY*NTOT*DIM];            // 12.6 MB
__device__ float g_U[(size_t)MTOT*NTOT];                 // 384 MB: 3 planes [p][m][512]
__device__ uint32_t g_mb[BATCH*(L_SEQ/32)];              // packed mask bits

// ---------------- helpers ---------------------------------------------------
__device__ __forceinline__ uint32_t smem_u32(const void* p) {
    uint32_t a;
    asm("{ .reg .u64 t; cvta.to.shared.u64 t, %1; cvt.u32.u64 %0, t; }"
        : "=r"(a) : "l"(p));
    return a;
}
__device__ __forceinline__ void cp16(uint32_t dst, const void* src) {
    asm volatile("cp.async.cg.shared.global [%0], [%1], 16;\n"
                 :: "r"(dst), "l"(src));
}
__device__ __forceinline__ void cp4(uint32_t dst, const void* src) {
    asm volatile("cp.async.ca.shared.global [%0], [%1], 4;\n"
                 :: "r"(dst), "l"(src));
}
#define CP_COMMIT() asm volatile("cp.async.commit_group;")
#define CP_WAIT(n)  asm volatile("cp.async.wait_group %0;" :: "n"(n) : "memory")

__device__ __forceinline__ uint32_t tf32r(float v) {
    uint32_t u;
    asm("cvt.rna.tf32.f32 %0, %1;" : "=r"(u) : "f"(v));
    return u;
}
__device__ __forceinline__ void lds128(uint32_t* r, uint32_t a) {
    asm volatile("ld.shared.v4.b32 {%0,%1,%2,%3}, [%4];"
                 : "=r"(r[0]), "=r"(r[1]), "=r"(r[2]), "=r"(r[3]) : "r"(a));
}
__device__ __forceinline__ void lds64(uint32_t* r, uint32_t a) {
    asm volatile("ld.shared.v2.b32 {%0,%1}, [%2];"
                 : "=r"(r[0]), "=r"(r[1]) : "r"(a));
}
__device__ __forceinline__ void mma_tf32(float* d, const uint32_t* a, const uint32_t* b) {
    asm volatile("mma.sync.aligned.m16n8k8.row.col.f32.tf32.tf32.f32 "
                 "{%0,%1,%2,%3}, {%4,%5,%6,%7}, {%8,%9}, {%0,%1,%2,%3};"
                 : "+f"(d[0]), "+f"(d[1]), "+f"(d[2]), "+f"(d[3])
                 : "r"(a[0]), "r"(a[1]), "r"(a[2]), "r"(a[3]),
                   "r"(b[0]), "r"(b[1]));
}

// fragment-order addressing
__device__ __forceinline__ size_t fragA(int m, int k) {
    return ((size_t)(m >> 4) * 64 + (k >> 3)) * 128 +
           (size_t)((((m & 7) * 4 + (k & 3)) * 4) + ((m >> 3) & 1) + 2 * ((k >> 2) & 1));
}
__device__ __forceinline__ size_t fragB(int n, int k) {
    return ((size_t)(n >> 3) * 64 + (k >> 3)) * 64 +
           (size_t)((((n & 7) * 4 + (k & 3)) * 2) + ((k >> 2) & 1));
}

// ---------------- GEMM config ----------------------------------------------
// CTA tile 128x128, K-chunk 32, 3-stage pipeline, 2 CTAs/SM.
// Warp tile 32x64 (4 warps along M, 2 along N) -> 192 B LDS per MMA.
#define MT 128
#define NT 128
#define KC 32
#define NCHUNK (DIM/KC)      // 16
#define OFF_B  16384         // A: 16 KB, B: 16 KB per stage
#define STAGE  32768
#define NSTAGE 3
#define SMEM_TOTAL (NSTAGE*STAGE)   // 98304

// kb0 in units of k8-blocks (4 per stage)
__device__ __forceinline__ void load_stage(uint32_t st, int mb0, int nb0, int kb0,
                                           const float* __restrict__ A,
                                           const float* __restrict__ B, int tid)
{
    #pragma unroll
    for (int it = 0; it < 4; it++) {       // A: 1024 x 16B  [m16 8][kb 4][128]
        int i = tid + it * 256;
        int mbl = i >> 7, rem = i & 127;
        int kbl = rem >> 5, cc = rem & 31;
        const float* src = A + ((size_t)(mb0 + mbl) * 64 + (kb0 + kbl)) * 128 + cc * 4;
        cp16(st + (uint32_t)i * 16u, src);
    }
    #pragma unroll
    for (int it = 0; it < 4; it++) {       // B: 1024 x 16B  [n8 16][kb 4][64]
        int i = tid + it * 256;
        int nbl = i >> 6, rem = i & 63;
        int kbl = rem >> 4, cc = rem & 15;
        const float* src = B + ((size_t)(nb0 + nbl) * 64 + (kb0 + kbl)) * 64 + cc * 4;
        cp16(st + OFF_B + (uint32_t)i * 16u, src);
    }
    CP_COMMIT();
}

struct FragT { uint32_t a[2][4]; uint32_t b[8][2]; };

__device__ __forceinline__ void load_frag(FragT& f, uint32_t st, int kb,
                                          int wm, int wn, int lane)
{
    #pragma unroll
    for (int mt = 0; mt < 2; mt++)
        lds128(f.a[mt], st + (uint32_t)((((wm * 2 + mt) * 4 + kb) * 128 + lane * 4) * 4));
    #pragma unroll
    for (int nt = 0; nt < 8; nt++)
        lds64(f.b[nt], st + OFF_B +
              (uint32_t)((((wn * 8 + nt) * 4 + kb) * 64 + lane * 2) * 4));
}
__device__ __forceinline__ void mma_all(float acc[2][8][4], const FragT& f)
{
    #pragma unroll
    for (int mt = 0; mt < 2; mt++)
        #pragma unroll
        for (int nt = 0; nt < 8; nt++)
            mma_tf32(acc[mt][nt], f.a[mt], f.b[nt]);
}

__global__ void __launch_bounds__(256, 2)
gemm_kernel(int layer, int n_tiles)
{
    extern __shared__ __align__(1024) char smem[];
    uint32_t sb = smem_u32(smem);
    int tid  = threadIdx.x;
    int wid  = tid >> 5, lane = tid & 31;
    int wm   = wid & 3;          // 4 warps along M (32 rows)
    int wn   = wid >> 2;         // 2 warps along N (64 cols)
    int m0   = (blockIdx.x / n_tiles) * MT;
    int n0   = (blockIdx.x % n_tiles) * NT;
    int mb0  = m0 >> 4;
    int nb0  = n0 >> 3;

    const float* A = g_hf;
    const float* B = g_Wf + (size_t)layer * NTOT * DIM;

    float acc[2][8][4];
    #pragma unroll
    for (int i = 0; i < 2; i++)
        #pragma unroll
        for (int j = 0; j < 8; j++)
            #pragma unroll
            for (int q = 0; q < 4; q++) acc[i][j][q] = 0.f;

    load_stage(sb,         mb0, nb0, 0, A, B, tid);
    load_stage(sb + STAGE, mb0, nb0, 4, A, B, tid);

    for (int chunk = 0; chunk < NCHUNK; ++chunk) {
        if (chunk < NCHUNK - 1) CP_WAIT(1);
        else                    CP_WAIT(0);
        __syncthreads();

        if (chunk + 2 < NCHUNK)
            load_stage(sb + (uint32_t)((chunk + 2) % NSTAGE) * STAGE,
                       mb0, nb0, (chunk + 2) * 4, A, B, tid);

        uint32_t st = sb + (uint32_t)(chunk % NSTAGE) * STAGE;
        FragT f;
        #pragma unroll
        for (int kb = 0; kb < 4; kb++) {
            load_frag(f, st, kb, wm, wn, lane);
            mma_all(acc, f);
        }
    }

    // epilogue: write U into planar layout [plane][m][512]
    int plane = n0 >> 9;
    int nc0   = n0 & 511;
    float* Up = g_U + (size_t)plane * PS;
    int rbase = lane >> 2;
    int cbase = (lane & 3) * 2;
    #pragma unroll
    for (int mt = 0; mt < 2; mt++) {
        int mrow = m0 + wm * 32 + mt * 16 + rbase;
        #pragma unroll
        for (int nt = 0; nt < 8; nt++) {
            int ncol = nc0 + wn * 64 + nt * 8 + cbase;
            *(float2*)(Up + (size_t)mrow * DIM + ncol) =
                make_float2(acc[mt][nt][0], acc[mt][nt][1]);
            *(float2*)(Up + (size_t)(mrow + 8) * DIM + ncol) =
                make_float2(acc[mt][nt][2], acc[mt][nt][3]);
        }
    }
}

// ---------------- pre-passes -------------------------------------------------
// x[b][t][d] fp32 -> g_hf fragment order (tf32-rounded), m = t*32+b
__global__ void __launch_bounds__(128)
split_x_kernel(const float* __restrict__ x)
{
    int e = blockIdx.x;                  // e = b*L + t
    int b = e >> 11, t = e & (L_SEQ - 1);
    int m = t * 32 + b;
    float4 v = ((const float4*)(x + (size_t)e * DIM))[threadIdx.x];
    int d0 = threadIdx.x * 4;
    g_hf[fragA(m, d0 + 0)] = __uint_as_float(tf32r(v.x));
    g_hf[fragA(m, d0 + 1)] = __uint_as_float(tf32r(v.y));
    g_hf[fragA(m, d0 + 2)] = __uint_as_float(tf32r(v.z));
    g_hf[fragA(m, d0 + 3)] = __uint_as_float(tf32r(v.w));
}

// W[l][k][n] fp32 -> g_Wf fragment order (tf32-rounded)
__global__ void __launch_bounds__(256)
split_w_kernel(const float* __restrict__ W)
{
    int o = blockIdx.x * 256 + threadIdx.x;   // [l][k][n] linear (coalesced read)
    int l = o / (DIM * NTOT);
    int rem = o - l * (DIM * NTOT);
    int k = rem / NTOT, n = rem - k * NTOT;
    float w = W[o];
    g_Wf[(size_t)l * NTOT * DIM + fragB(n, k)] = __uint_as_float(tf32r(w));
}

__global__ void __launch_bounds__(64)
pack_mask_kernel(const int* __restrict__ mask)
{
    int b = blockIdx.x, w = threadIdx.x;   // grid 32, block 64
    uint32_t bits = 0;
    #pragma unroll 8
    for (int i = 0; i < 32; i++)
        bits |= (mask[b * L_SEQ + w * 32 + i] != 0 ? 1u : 0u) << i;
    g_mb[b * (L_SEQ/32) + w] = bits;
}

// ---------------- recurrence -------------------------------------------------
// 1 thread per (b,d) chain; u streamed via cp.async -> smem, double-buffered.
#define RB 16
#define NB (L_SEQ/RB)          // 128
#define RSMEM (2*RB*3*128*4)   // 49152 bytes

template<bool LAST>
__device__ __forceinline__ void recur_issue(uint32_t sbase, int s, int t0, int tid,
    const float* __restrict__ p0, const float* __restrict__ p1,
    const float* __restrict__ p2)
{
    #pragma unroll
    for (int j = 0; j < RB; j++) {
        uint32_t dst = sbase + (uint32_t)(((s * RB + j) * 3) * 128 + tid) * 4u;
        size_t go = (size_t)(t0 + j) * TSTRIDE;
        cp4(dst,        p0 + go);
        cp4(dst + 512,  p1 + go);
        if (!LAST) cp4(dst + 1024, p2 + go);
    }
    CP_COMMIT();
}

template<bool LAST>
__device__ __forceinline__ void recur_loadx(float* xv, int t0,
                                            const float* __restrict__ hf)
{
    if (!LAST) {
        #pragma unroll
        for (int j = 0; j < RB; j++)
            xv[j] = hf[(size_t)(t0 + j) * TSTRIDE];
    }
}

template<bool LAST>
__device__ __forceinline__ void recur_compute(const float* __restrict__ su,
    int s, int tid, const float* xv, int t0, uint32_t mw, float& c,
    float vf, float vr, float bf, float br, float* __restrict__ hf)
{
    int shb = t0 & 31;
    #pragma unroll
    for (int j = 0; j < RB; j++) {
        const float* sp = su + ((s * RB + j) * 3) * 128 + tid;
        float u0 = sp[0];
        float u1 = sp[128];
        bool pad = ((mw >> (shb + j)) & 1u) == 0u;
        float z = fmaf(vf, c, u1 + bf);
        float f = __fdividef(1.f, 1.f + __expf(-z));
        float cn = fmaf(f, c - u0, u0);
        c = pad ? c : cn;
        if (!LAST) {
            float u2 = sp[256];
            float xvj = xv[j];
            float z2 = fmaf(vr, c, u2 + br);
            float r  = __fdividef(1.f, 1.f + __expf(-z2));
            float ht = pad ? 0.f : fmaf(r, c - xvj, xvj);
            hf[(size_t)(t0 + j) * TSTRIDE] = __uint_as_float(tf32r(ht));
        }
    }
}

template<bool LAST>
__global__ void __launch_bounds__(128)
recur_kernel(const float* __restrict__ state, const float* __restrict__ vc,
             const float* __restrict__ bias, float* __restrict__ out, int layer)
{
    extern __shared__ float su[];       // [2][RB][3][128]
    int tid = threadIdx.x;
    int g = blockIdx.x * 128 + tid;
    int b = g >> 9, d = g & (DIM - 1);
    float vf = vc[layer * 2 * DIM + d];
    float vr = LAST ? 0.f : vc[layer * 2 * DIM + DIM + d];
    float bf = bias[layer * 2 * DIM + d];
    float br = LAST ? 0.f : bias[layer * 2 * DIM + DIM + d];
    float c  = state[layer * DIM + d];

    size_t roff = (size_t)b * DIM + d;                 // U planar offset
    const float* p0 = g_U + roff;
    const float* p1 = g_U + PS + roff;
    const float* p2 = g_U + 2 * PS + roff;
    // h (x) base in fragment order, t-stride = TSTRIDE
    float* hf = g_hf + ((size_t)(b >> 4) * 64 + (d >> 3)) * 128
                + (size_t)((((b & 7) * 4 + (d & 3)) * 4) + ((b >> 3) & 1) + 2 * ((d >> 2) & 1));
    const uint32_t* mb = g_mb + b * (L_SEQ/32);
    uint32_t sbase = smem_u32(su);

    float xvA[RB], xvB[RB];

    recur_issue<LAST>(sbase, 0, 0, tid, p0, p1, p2);
    recur_loadx<LAST>(xvA, 0, hf);
    uint32_t mw = mb[0];

    for (int blk = 0; blk < NB; blk += 2) {
        int t0 = blk * RB;
        recur_issue<LAST>(sbase, 1, t0 + RB, tid, p0, p1, p2);
        recur_loadx<LAST>(xvB, t0 + RB, hf);
        int nw = (blk >> 1) + 1;
        uint32_t mwn = mb[nw < (L_SEQ/32) ? nw : (L_SEQ/32) - 1];

        CP_WAIT(1);
        recur_compute<LAST>(su, 0, tid, xvA, t0, mw, c, vf, vr, bf, br, hf);

        if (blk + 2 < NB) {
            recur_issue<LAST>(sbase, 0, t0 + 2 * RB, tid, p0, p1, p2);
            recur_loadx<LAST>(xvA, t0 + 2 * RB, hf);
            CP_WAIT(1);
        } else {
            CP_WAIT(0);
        }
        recur_compute<LAST>(su, 1, tid, xvB, t0 + RB, mw, c, vf, vr, bf, br, hf);
        mw = mwn;
    }

    if (layer == 0) out[g] = c;
    else            out[g] += c;
}

// ---------------- launch -----------------------------------------------------
extern "C" void kernel_launch(void* const* d_in, const int* in_sizes, int n_in,
                              void* d_out, int out_size)
{
    const float* x     = (const float*)d_in[0];
    const int*   mask  = (const int*)  d_in[1];
    const float* state = (const float*)d_in[2];
    const float* W     = (const float*)d_in[3];
    const float* vc    = (const float*)d_in[4];
    const float* bias  = (const float*)d_in[5];
    float* out = (float*)d_out;

    cudaFuncSetAttribute(gemm_kernel,
                         cudaFuncAttributeMaxDynamicSharedMemorySize, SMEM_TOTAL);
    cudaFuncSetAttribute(recur_kernel<false>,
                         cudaFuncAttributeMaxDynamicSharedMemorySize, RSMEM);
    cudaFuncSetAttribute(recur_kernel<true>,
                         cudaFuncAttributeMaxDynamicSharedMemorySize, RSMEM);

    split_x_kernel<<<BATCH * L_SEQ, 128>>>(x);
    split_w_kernel<<<(NLAY * NTOT * DIM) / 256, 256>>>(W);
    pack_mask_kernel<<<BATCH, 64>>>(mask);

    for (int l = 0; l < NLAY; l++) {
        int nt = (l == NLAY - 1) ? 8 : 12;   // last layer: skip u2 tiles
        gemm_kernel<<<(MTOT / MT) * nt, 256, SMEM_TOTAL>>>(l, nt);
        if (l == NLAY - 1)
            recur_kernel<true><<<(BATCH * DIM) / 128, 128, RSMEM>>>(state, vc, bias, out, l);
        else
            recur_kernel<false><<<(BATCH * DIM) / 128, 128, RSMEM>>>(state, vc, bias, out, l);
    }
    (void)in_sizes; (void)n_in; (void)out_size;
}

// round 11
// speedup vs baseline: 2.4331x; 1.4145x over previous
#include <cuda_runtime.h>
#include <cuda_fp16.h>
#include <cstdint>
#include <cstddef>

// Problem constants
#define L_SEQ  2048
#define BATCH  32
#define DIM    512
#define NLAY   4
#define MTOT   (L_SEQ*BATCH)   // 65536
#define NTOT   (3*DIM)         // 1536
#define PS     ((size_t)MTOT*DIM)       // floats per U plane
#define TSTRIDE 16384                   // floats per t-step in U plane (32*512)
#define HSTRIDE 16384                   // halves per t-step in g_hh (2*32*256)

// ---------------- device-global scratch ------------------------------------
// g_hh: A operand / h state, fp16, m16n8k16-fragment order:
//   [m16_blk 4096][k16_blk 32][256 halves]
__device__ __half g_hh[(size_t)MTOT*DIM];                // 64 MB
// g_Wh: B operand fp16, per layer: [n8_blk 192][k16_blk 32][128 halves]
__device__ __half g_Wh[(size_t)NLAY*NTOT*DIM];           // 6.3 MB
__device__ float  g_U[(size_t)MTOT*NTOT];                // 384 MB: 3 planes [p][m][512]
__device__ uint32_t g_mb[BATCH*(L_SEQ/32)];              // packed mask bits

// ---------------- helpers ---------------------------------------------------
__device__ __forceinline__ uint32_t smem_u32(const void* p) {
    uint32_t a;
    asm("{ .reg .u64 t; cvta.to.shared.u64 t, %1; cvt.u32.u64 %0, t; }"
        : "=r"(a) : "l"(p));
    return a;
}
__device__ __forceinline__ void cp16(uint32_t dst, const void* src) {
    asm volatile("cp.async.cg.shared.global [%0], [%1], 16;\n"
                 :: "r"(dst), "l"(src));
}
__device__ __forceinline__ void cp4(uint32_t dst, const void* src) {
    asm volatile("cp.async.ca.shared.global [%0], [%1], 4;\n"
                 :: "r"(dst), "l"(src));
}
#define CP_COMMIT() asm volatile("cp.async.commit_group;")
#define CP_WAIT(n)  asm volatile("cp.async.wait_group %0;" :: "n"(n) : "memory")

__device__ __forceinline__ void lds128(uint32_t* r, uint32_t a) {
    asm volatile("ld.shared.v4.b32 {%0,%1,%2,%3}, [%4];"
                 : "=r"(r[0]), "=r"(r[1]), "=r"(r[2]), "=r"(r[3]) : "r"(a));
}
__device__ __forceinline__ void lds64(uint32_t* r, uint32_t a) {
    asm volatile("ld.shared.v2.b32 {%0,%1}, [%2];"
                 : "=r"(r[0]), "=r"(r[1]) : "r"(a));
}
__device__ __forceinline__ void mma_f16(float* d, const uint32_t* a, const uint32_t* b) {
    asm volatile("mma.sync.aligned.m16n8k16.row.col.f32.f16.f16.f32 "
                 "{%0,%1,%2,%3}, {%4,%5,%6,%7}, {%8,%9}, {%0,%1,%2,%3};"
                 : "+f"(d[0]), "+f"(d[1]), "+f"(d[2]), "+f"(d[3])
                 : "r"(a[0]), "r"(a[1]), "r"(a[2]), "r"(a[3]),
                   "r"(b[0]), "r"(b[1]));
}

// fragment-order addressing (half-element index)
__device__ __forceinline__ size_t fragA16(int m, int k) {
    size_t blk = (size_t)(m >> 4) * 32 + (k >> 4);
    int lane = ((m & 7) << 2) | ((k & 7) >> 1);
    int reg  = ((m >> 3) & 1) + 2 * ((k >> 3) & 1);
    return blk * 256 + (size_t)((lane * 4 + reg) * 2 + (k & 1));
}
__device__ __forceinline__ size_t fragB16(int n, int k) {
    size_t blk = (size_t)(n >> 3) * 32 + (k >> 4);
    int lane = ((n & 7) << 2) | ((k & 7) >> 1);
    int reg  = (k >> 3) & 1;
    return blk * 128 + (size_t)((lane * 2 + reg) * 2 + (k & 1));
}

// ---------------- GEMM config ----------------------------------------------
// CTA tile 128x128, K-chunk 64 (4 k16-blocks), 3-stage pipeline, 2 CTAs/SM.
// Warp tile 32x64 (4 warps M, 2 warps N).
#define MT 128
#define NT 128
#define KC 64
#define NCHUNK (DIM/KC)      // 8
#define OFF_B  16384         // A: 16 KB, B: 16 KB per stage
#define STAGE  32768
#define NSTAGE 3
#define SMEM_TOTAL (NSTAGE*STAGE)   // 98304

// kb0 in units of k16-blocks (4 per stage)
__device__ __forceinline__ void load_stage(uint32_t st, int mb0, int nb0, int kb0,
                                           const __half* __restrict__ A,
                                           const __half* __restrict__ B, int tid)
{
    #pragma unroll
    for (int it = 0; it < 4; it++) {       // A: 1024 x 16B  [m16 8][kb 4][512B]
        int i = tid + it * 256;
        int mbl = i >> 7, rem = i & 127;
        int kbl = rem >> 5, cc = rem & 31;
        const __half* src = A + ((size_t)(mb0 + mbl) * 32 + (kb0 + kbl)) * 256 + cc * 8;
        cp16(st + (uint32_t)i * 16u, src);
    }
    #pragma unroll
    for (int it = 0; it < 4; it++) {       // B: 1024 x 16B  [n8 16][kb 4][256B]
        int i = tid + it * 256;
        int nbl = i >> 6, rem = i & 63;
        int kbl = rem >> 4, cc = rem & 15;
        const __half* src = B + ((size_t)(nb0 + nbl) * 32 + (kb0 + kbl)) * 128 + cc * 8;
        cp16(st + OFF_B + (uint32_t)i * 16u, src);
    }
    CP_COMMIT();
}

struct FragT { uint32_t a[2][4]; uint32_t b[8][2]; };

__device__ __forceinline__ void load_frag(FragT& f, uint32_t st, int kb,
                                          int wm, int wn, int lane)
{
    #pragma unroll
    for (int mt = 0; mt < 2; mt++)
        lds128(f.a[mt], st + (uint32_t)((((wm * 2 + mt) * 4 + kb) * 512) + lane * 16));
    #pragma unroll
    for (int nt = 0; nt < 8; nt++)
        lds64(f.b[nt], st + OFF_B +
              (uint32_t)((((wn * 8 + nt) * 4 + kb) * 256) + lane * 8));
}
__device__ __forceinline__ void mma_all(float acc[2][8][4], const FragT& f)
{
    #pragma unroll
    for (int mt = 0; mt < 2; mt++)
        #pragma unroll
        for (int nt = 0; nt < 8; nt++)
            mma_f16(acc[mt][nt], f.a[mt], f.b[nt]);
}

__global__ void __launch_bounds__(256, 2)
gemm_kernel(int layer, int n_tiles)
{
    extern __shared__ __align__(1024) char smem[];
    uint32_t sb = smem_u32(smem);
    int tid  = threadIdx.x;
    int wid  = tid >> 5, lane = tid & 31;
    int wm   = wid & 3;          // 4 warps along M (32 rows)
    int wn   = wid >> 2;         // 2 warps along N (64 cols)
    int m0   = (blockIdx.x / n_tiles) * MT;
    int n0   = (blockIdx.x % n_tiles) * NT;
    int mb0  = m0 >> 4;          // m16 blocks
    int nb0  = n0 >> 3;          // n8 blocks

    const __half* A = g_hh;
    const __half* B = g_Wh + (size_t)layer * NTOT * DIM;

    float acc[2][8][4];
    #pragma unroll
    for (int i = 0; i < 2; i++)
        #pragma unroll
        for (int j = 0; j < 8; j++)
            #pragma unroll
            for (int q = 0; q < 4; q++) acc[i][j][q] = 0.f;

    load_stage(sb,         mb0, nb0, 0, A, B, tid);
    load_stage(sb + STAGE, mb0, nb0, 4, A, B, tid);

    for (int chunk = 0; chunk < NCHUNK; ++chunk) {
        if (chunk < NCHUNK - 1) CP_WAIT(1);
        else                    CP_WAIT(0);
        __syncthreads();

        if (chunk + 2 < NCHUNK)
            load_stage(sb + (uint32_t)((chunk + 2) % NSTAGE) * STAGE,
                       mb0, nb0, (chunk + 2) * 4, A, B, tid);

        uint32_t st = sb + (uint32_t)(chunk % NSTAGE) * STAGE;
        FragT f;
        #pragma unroll
        for (int kb = 0; kb < 4; kb++) {
            load_frag(f, st, kb, wm, wn, lane);
            mma_all(acc, f);
        }
    }

    // epilogue: write U (fp32) into planar layout [plane][m][512]
    int plane = n0 >> 9;
    int nc0   = n0 & 511;
    float* Up = g_U + (size_t)plane * PS;
    int rbase = lane >> 2;
    int cbase = (lane & 3) * 2;
    #pragma unroll
    for (int mt = 0; mt < 2; mt++) {
        int mrow = m0 + wm * 32 + mt * 16 + rbase;
        #pragma unroll
        for (int nt = 0; nt < 8; nt++) {
            int ncol = nc0 + wn * 64 + nt * 8 + cbase;
            *(float2*)(Up + (size_t)mrow * DIM + ncol) =
                make_float2(acc[mt][nt][0], acc[mt][nt][1]);
            *(float2*)(Up + (size_t)(mrow + 8) * DIM + ncol) =
                make_float2(acc[mt][nt][2], acc[mt][nt][3]);
        }
    }
}

// ---------------- pre-passes -------------------------------------------------
// x[b][t][d] fp32 -> g_hh fp16 fragment order, m = t*32+b
__global__ void __launch_bounds__(128)
split_x_kernel(const float* __restrict__ x)
{
    int e = blockIdx.x;                  // e = b*L + t
    int b = e >> 11, t = e & (L_SEQ - 1);
    int m = t * 32 + b;
    float4 v = ((const float4*)(x + (size_t)e * DIM))[threadIdx.x];
    int d0 = threadIdx.x * 4;
    g_hh[fragA16(m, d0 + 0)] = __float2half_rn(v.x);
    g_hh[fragA16(m, d0 + 1)] = __float2half_rn(v.y);
    g_hh[fragA16(m, d0 + 2)] = __float2half_rn(v.z);
    g_hh[fragA16(m, d0 + 3)] = __float2half_rn(v.w);
}

// W[l][k][n] fp32 -> g_Wh fp16 fragment order
__global__ void __launch_bounds__(256)
split_w_kernel(const float* __restrict__ W)
{
    int o = blockIdx.x * 256 + threadIdx.x;   // [l][k][n] linear (coalesced read)
    int l = o / (DIM * NTOT);
    int rem = o - l * (DIM * NTOT);
    int k = rem / NTOT, n = rem - k * NTOT;
    float w = W[o];
    g_Wh[(size_t)l * NTOT * DIM + fragB16(n, k)] = __float2half_rn(w);
}

__global__ void __launch_bounds__(64)
pack_mask_kernel(const int* __restrict__ mask)
{
    int b = blockIdx.x, w = threadIdx.x;   // grid 32, block 64
    uint32_t bits = 0;
    #pragma unroll 8
    for (int i = 0; i < 32; i++)
        bits |= (mask[b * L_SEQ + w * 32 + i] != 0 ? 1u : 0u) << i;
    g_mb[b * (L_SEQ/32) + w] = bits;
}

// ---------------- recurrence -------------------------------------------------
// 1 thread per (b,d) chain; U (fp32) streamed via cp.async -> smem.
#define RB 16
#define NB (L_SEQ/RB)          // 128
#define RSMEM (2*RB*3*128*4)   // 49152 bytes

template<bool LAST>
__device__ __forceinline__ void recur_issue(uint32_t sbase, int s, int t0, int tid,
    const float* __restrict__ p0, const float* __restrict__ p1,
    const float* __restrict__ p2)
{
    #pragma unroll
    for (int j = 0; j < RB; j++) {
        uint32_t dst = sbase + (uint32_t)(((s * RB + j) * 3) * 128 + tid) * 4u;
        size_t go = (size_t)(t0 + j) * TSTRIDE;
        cp4(dst,        p0 + go);
        cp4(dst + 512,  p1 + go);
        if (!LAST) cp4(dst + 1024, p2 + go);
    }
    CP_COMMIT();
}

template<bool LAST>
__device__ __forceinline__ void recur_loadx(float* xv, int t0,
                                            const __half* __restrict__ hf)
{
    if (!LAST) {
        #pragma unroll
        for (int j = 0; j < RB; j++)
            xv[j] = __half2float(hf[(size_t)(t0 + j) * HSTRIDE]);
    }
}

template<bool LAST>
__device__ __forceinline__ void recur_compute(const float* __restrict__ su,
    int s, int tid, const float* xv, int t0, uint32_t mw, float& c,
    float vf, float vr, float bf, float br, __half* __restrict__ hf)
{
    int shb = t0 & 31;
    #pragma unroll
    for (int j = 0; j < RB; j++) {
        const float* sp = su + ((s * RB + j) * 3) * 128 + tid;
        float u0 = sp[0];
        float u1 = sp[128];
        bool pad = ((mw >> (shb + j)) & 1u) == 0u;
        float z = fmaf(vf, c, u1 + bf);
        float f = __fdividef(1.f, 1.f + __expf(-z));
        float cn = fmaf(f, c - u0, u0);
        c = pad ? c : cn;
        if (!LAST) {
            float u2 = sp[256];
            float xvj = xv[j];
            float z2 = fmaf(vr, c, u2 + br);
            float r  = __fdividef(1.f, 1.f + __expf(-z2));
            float ht = pad ? 0.f : fmaf(r, c - xvj, xvj);
            hf[(size_t)(t0 + j) * HSTRIDE] = __float2half_rn(ht);
        }
    }
}

template<bool LAST>
__global__ void __launch_bounds__(128)
recur_kernel(const float* __restrict__ state, const float* __restrict__ vc,
             const float* __restrict__ bias, float* __restrict__ out, int layer)
{
    extern __shared__ float su[];       // [2][RB][3][128]
    int tid = threadIdx.x;
    int g = blockIdx.x * 128 + tid;
    int b = g >> 9, d = g & (DIM - 1);
    float vf = vc[layer * 2 * DIM + d];
    float vr = LAST ? 0.f : vc[layer * 2 * DIM + DIM + d];
    float bf = bias[layer * 2 * DIM + d];
    float br = LAST ? 0.f : bias[layer * 2 * DIM + DIM + d];
    float c  = state[layer * DIM + d];

    size_t roff = (size_t)b * DIM + d;                 // U planar offset
    const float* p0 = g_U + roff;
    const float* p1 = g_U + PS + roff;
    const float* p2 = g_U + 2 * PS + roff;
    // h (x) base in fp16 fragment order; t-stride = HSTRIDE (m = t*32+b)
    __half* hf = g_hh + fragA16(b, d);
    const uint32_t* mb = g_mb + b * (L_SEQ/32);
    uint32_t sbase = smem_u32(su);

    float xvA[RB], xvB[RB];

    recur_issue<LAST>(sbase, 0, 0, tid, p0, p1, p2);
    recur_loadx<LAST>(xvA, 0, hf);
    uint32_t mw = mb[0];

    for (int blk = 0; blk < NB; blk += 2) {
        int t0 = blk * RB;
        recur_issue<LAST>(sbase, 1, t0 + RB, tid, p0, p1, p2);
        recur_loadx<LAST>(xvB, t0 + RB, hf);
        int nw = (blk >> 1) + 1;
        uint32_t mwn = mb[nw < (L_SEQ/32) ? nw : (L_SEQ/32) - 1];

        CP_WAIT(1);
        recur_compute<LAST>(su, 0, tid, xvA, t0, mw, c, vf, vr, bf, br, hf);

        if (blk + 2 < NB) {
            recur_issue<LAST>(sbase, 0, t0 + 2 * RB, tid, p0, p1, p2);
            recur_loadx<LAST>(xvA, t0 + 2 * RB, hf);
            CP_WAIT(1);
        } else {
            CP_WAIT(0);
        }
        recur_compute<LAST>(su, 1, tid, xvB, t0 + RB, mw, c, vf, vr, bf, br, hf);
        mw = mwn;
    }

    if (layer == 0) out[g] = c;
    else            out[g] += c;
}

// ---------------- launch -----------------------------------------------------
extern "C" void kernel_launch(void* const* d_in, const int* in_sizes, int n_in,
                              void* d_out, int out_size)
{
    const float* x     = (const float*)d_in[0];
    const int*   mask  = (const int*)  d_in[1];
    const float* state = (const float*)d_in[2];
    const float* W     = (const float*)d_in[3];
    const float* vc    = (const float*)d_in[4];
    const float* bias  = (const float*)d_in[5];
    float* out = (float*)d_out;

    cudaFuncSetAttribute(gemm_kernel,
                         cudaFuncAttributeMaxDynamicSharedMemorySize, SMEM_TOTAL);
    cudaFuncSetAttribute(recur_kernel<false>,
                         cudaFuncAttributeMaxDynamicSharedMemorySize, RSMEM);
    cudaFuncSetAttribute(recur_kernel<true>,
                         cudaFuncAttributeMaxDynamicSharedMemorySize, RSMEM);

    split_x_kernel<<<BATCH * L_SEQ, 128>>>(x);
    split_w_kernel<<<(NLAY * NTOT * DIM) / 256, 256>>>(W);
    pack_mask_kernel<<<BATCH, 64>>>(mask);

    for (int l = 0; l < NLAY; l++) {
        int nt = (l == NLAY - 1) ? 8 : 12;   // last layer: skip u2 tiles
        gemm_kernel<<<(MTOT / MT) * nt, 256, SMEM_TOTAL>>>(l, nt);
        if (l == NLAY - 1)
            recur_kernel<true><<<(BATCH * DIM) / 128, 128, RSMEM>>>(state, vc, bias, out, l);
        else
            recur_kernel<false><<<(BATCH * DIM) / 128, 128, RSMEM>>>(state, vc, bias, out, l);
    }
    (void)in_sizes; (void)n_in; (void)out_size;
}

// round 12
// speedup vs baseline: 2.8847x; 1.1856x over previous
#include <cuda_runtime.h>
#include <cuda_fp16.h>
#include <cstdint>
#include <cstddef>

// Problem constants
#define L_SEQ  2048
#define BATCH  32
#define DIM    512
#define NLAY   4
#define MTOT   (L_SEQ*BATCH)   // 65536
#define NTOT   (3*DIM)         // 1536
#define PS     ((size_t)MTOT*DIM)       // floats per U plane
#define TSTRIDE 16384                   // floats per t-step in U plane (32*512)
#define HSTRIDE 16384                   // halves per t-step in fragment space
#define L2E    1.4426950408889634f

// ---------------- device-global scratch ------------------------------------
__device__ __half g_hh[(size_t)MTOT*DIM];                // 64 MB  h/x, frag order
__device__ __half g_Wh[(size_t)NLAY*NTOT*DIM];           // 6.3 MB W fp16 frag order
__device__ float  g_U[(size_t)MTOT*DIM*2];               // 256 MB: planes u0,u1 planar
__device__ __half g_u2h[(size_t)MTOT*DIM];               // 64 MB  u2 fp16 frag order
__device__ __half g_ch[(size_t)MTOT*DIM];                // 64 MB  c fp16 frag order
__device__ uint32_t g_mb[BATCH*(L_SEQ/32)];              // mask bits, b-major
__device__ uint32_t g_mbt[L_SEQ];                        // mask bits, t-major (bit=b)

// ---------------- helpers ---------------------------------------------------
__device__ __forceinline__ uint32_t smem_u32(const void* p) {
    uint32_t a;
    asm("{ .reg .u64 t; cvta.to.shared.u64 t, %1; cvt.u32.u64 %0, t; }"
        : "=r"(a) : "l"(p));
    return a;
}
__device__ __forceinline__ void cp16(uint32_t dst, const void* src) {
    asm volatile("cp.async.cg.shared.global [%0], [%1], 16;\n"
                 :: "r"(dst), "l"(src));
}
__device__ __forceinline__ void cp4(uint32_t dst, const void* src) {
    asm volatile("cp.async.ca.shared.global [%0], [%1], 4;\n"
                 :: "r"(dst), "l"(src));
}
#define CP_COMMIT() asm volatile("cp.async.commit_group;")
#define CP_WAIT(n)  asm volatile("cp.async.wait_group %0;" :: "n"(n) : "memory")

__device__ __forceinline__ float ex2f(float x) {
    float r; asm("ex2.approx.f32 %0, %1;" : "=f"(r) : "f"(x)); return r;
}
__device__ __forceinline__ float rcpf(float x) {
    float r; asm("rcp.approx.f32 %0, %1;" : "=f"(r) : "f"(x)); return r;
}
__device__ __forceinline__ void lds128(uint32_t* r, uint32_t a) {
    asm volatile("ld.shared.v4.b32 {%0,%1,%2,%3}, [%4];"
                 : "=r"(r[0]), "=r"(r[1]), "=r"(r[2]), "=r"(r[3]) : "r"(a));
}
__device__ __forceinline__ void lds64(uint32_t* r, uint32_t a) {
    asm volatile("ld.shared.v2.b32 {%0,%1}, [%2];"
                 : "=r"(r[0]), "=r"(r[1]) : "r"(a));
}
__device__ __forceinline__ void mma_f16(float* d, const uint32_t* a, const uint32_t* b) {
    asm volatile("mma.sync.aligned.m16n8k16.row.col.f32.f16.f16.f32 "
                 "{%0,%1,%2,%3}, {%4,%5,%6,%7}, {%8,%9}, {%0,%1,%2,%3};"
                 : "+f"(d[0]), "+f"(d[1]), "+f"(d[2]), "+f"(d[3])
                 : "r"(a[0]), "r"(a[1]), "r"(a[2]), "r"(a[3]),
                   "r"(b[0]), "r"(b[1]));
}

// fragment-order addressing (half-element index), m16n8k16
__device__ __forceinline__ size_t fragA16(int m, int k) {
    size_t blk = (size_t)(m >> 4) * 32 + (k >> 4);
    int lane = ((m & 7) << 2) | ((k & 7) >> 1);
    int reg  = ((m >> 3) & 1) + 2 * ((k >> 3) & 1);
    return blk * 256 + (size_t)((lane * 4 + reg) * 2 + (k & 1));
}
__device__ __forceinline__ size_t fragB16(int n, int k) {
    size_t blk = (size_t)(n >> 3) * 32 + (k >> 4);
    int lane = ((n & 7) << 2) | ((k & 7) >> 1);
    int reg  = (k >> 3) & 1;
    return blk * 128 + (size_t)((lane * 2 + reg) * 2 + (k & 1));
}

// ---------------- GEMM -------------------------------------------------------
#define MT 128
#define NT 128
#define KC 64
#define NCHUNK (DIM/KC)      // 8
#define OFF_B  16384
#define STAGE  32768
#define NSTAGE 3
#define SMEM_TOTAL (NSTAGE*STAGE)   // 98304

__device__ __forceinline__ void load_stage(uint32_t st, int mb0, int nb0, int kb0,
                                           const __half* __restrict__ A,
                                           const __half* __restrict__ B, int tid)
{
    #pragma unroll
    for (int it = 0; it < 4; it++) {       // A: [m16 8][kb 4][512B]
        int i = tid + it * 256;
        int mbl = i >> 7, rem = i & 127;
        int kbl = rem >> 5, cc = rem & 31;
        const __half* src = A + ((size_t)(mb0 + mbl) * 32 + (kb0 + kbl)) * 256 + cc * 8;
        cp16(st + (uint32_t)i * 16u, src);
    }
    #pragma unroll
    for (int it = 0; it < 4; it++) {       // B: [n8 16][kb 4][256B]
        int i = tid + it * 256;
        int nbl = i >> 6, rem = i & 63;
        int kbl = rem >> 4, cc = rem & 15;
        const __half* src = B + ((size_t)(nb0 + nbl) * 32 + (kb0 + kbl)) * 128 + cc * 8;
        cp16(st + OFF_B + (uint32_t)i * 16u, src);
    }
    CP_COMMIT();
}

struct FragT { uint32_t a[2][4]; uint32_t b[8][2]; };

__device__ __forceinline__ void load_frag(FragT& f, uint32_t st, int kb,
                                          int wm, int wn, int lane)
{
    #pragma unroll
    for (int mt = 0; mt < 2; mt++)
        lds128(f.a[mt], st + (uint32_t)((((wm * 2 + mt) * 4 + kb) * 512) + lane * 16));
    #pragma unroll
    for (int nt = 0; nt < 8; nt++)
        lds64(f.b[nt], st + OFF_B +
              (uint32_t)((((wn * 8 + nt) * 4 + kb) * 256) + lane * 8));
}
__device__ __forceinline__ void mma_all(float acc[2][8][4], const FragT& f)
{
    #pragma unroll
    for (int mt = 0; mt < 2; mt++)
        #pragma unroll
        for (int nt = 0; nt < 8; nt++)
            mma_f16(acc[mt][nt], f.a[mt], f.b[nt]);
}

__device__ __forceinline__ void store_u2h(int m, int k, float a, float b)
{
    size_t off = ((size_t)(m >> 4) * 32 + (k >> 4)) * 256
               + (size_t)(((((m & 7) << 2) | ((k & 7) >> 1)) * 4
                           + (((m >> 3) & 1) + 2 * ((k >> 3) & 1))) * 2);
    *(__half2*)(g_u2h + off) = __floats2half2_rn(a, b);
}

__global__ void __launch_bounds__(256, 2)
gemm_kernel(int layer, int n_tiles)
{
    extern __shared__ __align__(1024) char smem[];
    uint32_t sb = smem_u32(smem);
    int tid  = threadIdx.x;
    int wid  = tid >> 5, lane = tid & 31;
    int wm   = wid & 3;
    int wn   = wid >> 2;
    int m0   = (blockIdx.x / n_tiles) * MT;
    int n0   = (blockIdx.x % n_tiles) * NT;
    int mb0  = m0 >> 4;
    int nb0  = n0 >> 3;

    const __half* A = g_hh;
    const __half* B = g_Wh + (size_t)layer * NTOT * DIM;

    float acc[2][8][4];
    #pragma unroll
    for (int i = 0; i < 2; i++)
        #pragma unroll
        for (int j = 0; j < 8; j++)
            #pragma unroll
            for (int q = 0; q < 4; q++) acc[i][j][q] = 0.f;

    load_stage(sb,         mb0, nb0, 0, A, B, tid);
    load_stage(sb + STAGE, mb0, nb0, 4, A, B, tid);

    for (int chunk = 0; chunk < NCHUNK; ++chunk) {
        if (chunk < NCHUNK - 1) CP_WAIT(1);
        else                    CP_WAIT(0);
        __syncthreads();

        if (chunk + 2 < NCHUNK)
            load_stage(sb + (uint32_t)((chunk + 2) % NSTAGE) * STAGE,
                       mb0, nb0, (chunk + 2) * 4, A, B, tid);

        uint32_t st = sb + (uint32_t)(chunk % NSTAGE) * STAGE;
        FragT f;
        #pragma unroll
        for (int kb = 0; kb < 4; kb++) {
            load_frag(f, st, kb, wm, wn, lane);
            mma_all(acc, f);
        }
    }

    // epilogue
    int plane = n0 >> 9;
    int nc0   = n0 & 511;
    int rbase = lane >> 2;
    int cbase = (lane & 3) * 2;
    if (plane < 2) {
        float* Up = g_U + (size_t)plane * PS;
        #pragma unroll
        for (int mt = 0; mt < 2; mt++) {
            int mrow = m0 + wm * 32 + mt * 16 + rbase;
            #pragma unroll
            for (int nt = 0; nt < 8; nt++) {
                int ncol = nc0 + wn * 64 + nt * 8 + cbase;
                *(float2*)(Up + (size_t)mrow * DIM + ncol) =
                    make_float2(acc[mt][nt][0], acc[mt][nt][1]);
                *(float2*)(Up + (size_t)(mrow + 8) * DIM + ncol) =
                    make_float2(acc[mt][nt][2], acc[mt][nt][3]);
            }
        }
    } else {  // u2 -> fp16 fragment order
        #pragma unroll
        for (int mt = 0; mt < 2; mt++) {
            int mrow = m0 + wm * 32 + mt * 16 + rbase;
            #pragma unroll
            for (int nt = 0; nt < 8; nt++) {
                int k = nc0 + wn * 64 + nt * 8 + cbase;
                store_u2h(mrow,     k, acc[mt][nt][0], acc[mt][nt][1]);
                store_u2h(mrow + 8, k, acc[mt][nt][2], acc[mt][nt][3]);
            }
        }
    }
}

// ---------------- pre-passes -------------------------------------------------
__global__ void __launch_bounds__(128)
split_x_kernel(const float* __restrict__ x)
{
    int e = blockIdx.x;                  // e = b*L + t
    int b = e >> 11, t = e & (L_SEQ - 1);
    int m = t * 32 + b;
    float4 v = ((const float4*)(x + (size_t)e * DIM))[threadIdx.x];
    int d0 = threadIdx.x * 4;
    g_hh[fragA16(m, d0 + 0)] = __float2half_rn(v.x);
    g_hh[fragA16(m, d0 + 1)] = __float2half_rn(v.y);
    g_hh[fragA16(m, d0 + 2)] = __float2half_rn(v.z);
    g_hh[fragA16(m, d0 + 3)] = __float2half_rn(v.w);
}

__global__ void __launch_bounds__(256)
split_w_kernel(const float* __restrict__ W)
{
    int o = blockIdx.x * 256 + threadIdx.x;   // [l][k][n] linear
    int l = o / (DIM * NTOT);
    int rem = o - l * (DIM * NTOT);
    int k = rem / NTOT, n = rem - k * NTOT;
    float w = W[o];
    g_Wh[(size_t)l * NTOT * DIM + fragB16(n, k)] = __float2half_rn(w);
}

__global__ void __launch_bounds__(64)
pack_mask_kernel(const int* __restrict__ mask)
{
    int b = blockIdx.x, w = threadIdx.x;   // grid 32, block 64
    uint32_t bits = 0;
    #pragma unroll 8
    for (int i = 0; i < 32; i++)
        bits |= (mask[b * L_SEQ + w * 32 + i] != 0 ? 1u : 0u) << i;
    g_mb[b * (L_SEQ/32) + w] = bits;
}

__global__ void __launch_bounds__(128)
pack_mask_t_kernel(const int* __restrict__ mask)
{
    int t = blockIdx.x * 128 + threadIdx.x;   // 2048 threads
    uint32_t bits = 0;
    #pragma unroll 8
    for (int b = 0; b < 32; b++)
        bits |= (mask[b * L_SEQ + t] != 0 ? 1u : 0u) << b;
    g_mbt[t] = bits;
}

// ---------------- c-scan (serial chain only) ---------------------------------
#define RB 16
#define NB (L_SEQ/RB)          // 128
#define RSMEM (2*RB*2*128*4)   // 32768 bytes

__device__ __forceinline__ void cs_issue(uint32_t sbase, int s, int t0, int tid,
    const float* __restrict__ p0, const float* __restrict__ p1)
{
    #pragma unroll
    for (int j = 0; j < RB; j++) {
        uint32_t dst = sbase + (uint32_t)(((s * RB + j) * 2) * 128 + tid) * 4u;
        size_t go = (size_t)(t0 + j) * TSTRIDE;
        cp4(dst,       p0 + go);
        cp4(dst + 512, p1 + go);
    }
    CP_COMMIT();
}

template<bool LAST>
__device__ __forceinline__ void cs_compute(const float* __restrict__ su,
    int s, int tid, int t0, uint32_t mw, float& c,
    float vfl, float nlbf, __half* __restrict__ hc)
{
    int shb = t0 & 31;
    #pragma unroll
    for (int j = 0; j < RB; j++) {
        const float* sp = su + ((s * RB + j) * 2) * 128 + tid;
        float u0 = sp[0];
        float u1 = sp[128];
        float ulb = fmaf(-L2E, u1, nlbf);      // off-chain
        bool pad = ((mw >> (shb + j)) & 1u) == 0u;
        float cd = c - u0;                      // parallel with sigmoid
        float e  = ex2f(fmaf(vfl, c, ulb));    // e = exp(-z)
        float f  = rcpf(1.f + e);
        float cn = fmaf(f, cd, u0);
        c = pad ? c : cn;
        if (!LAST)
            hc[(size_t)(t0 + j) * HSTRIDE] = __float2half_rn(c);
    }
}

template<bool LAST>
__global__ void __launch_bounds__(128)
cscan_kernel(const float* __restrict__ state, const float* __restrict__ vc,
             const float* __restrict__ bias, float* __restrict__ out, int layer)
{
    extern __shared__ float su[];       // [2][RB][2][128]
    int tid = threadIdx.x;
    int g = blockIdx.x * 128 + tid;
    int b = g >> 9, d = g & (DIM - 1);
    float vf = vc[layer * 2 * DIM + d];
    float bf = bias[layer * 2 * DIM + d];
    float vfl  = -L2E * vf;
    float nlbf = -L2E * bf;
    float c  = state[layer * DIM + d];

    size_t roff = (size_t)b * DIM + d;
    const float* p0 = g_U + roff;
    const float* p1 = g_U + PS + roff;
    __half* hc = g_ch + fragA16(b, d);
    const uint32_t* mb = g_mb + b * (L_SEQ/32);
    uint32_t sbase = smem_u32(su);

    cs_issue(sbase, 0, 0, tid, p0, p1);
    uint32_t mw = mb[0];

    for (int blk = 0; blk < NB; blk += 2) {
        int t0 = blk * RB;
        cs_issue(sbase, 1, t0 + RB, tid, p0, p1);
        int nw = (blk >> 1) + 1;
        uint32_t mwn = mb[nw < (L_SEQ/32) ? nw : (L_SEQ/32) - 1];

        CP_WAIT(1);
        cs_compute<LAST>(su, 0, tid, t0, mw, c, vfl, nlbf, hc);

        if (blk + 2 < NB) {
            cs_issue(sbase, 0, t0 + 2 * RB, tid, p0, p1);
            CP_WAIT(1);
        } else {
            CP_WAIT(0);
        }
        cs_compute<LAST>(su, 1, tid, t0 + RB, mw, c, vfl, nlbf, hc);
        mw = mwn;
    }

    if (layer == 0) out[g] = c;
    else            out[g] += c;
}

// ---------------- h-update (fully parallel) ----------------------------------
// thread = one 8-half chunk; c, x(old h), u2 share fragment layout.
__global__ void __launch_bounds__(256)
hupdate_kernel(const float* __restrict__ vc, const float* __restrict__ bias,
               int layer)
{
    int g = blockIdx.x * 256 + threadIdx.x;   // chunk id (8 halves)
    int blk  = g >> 5;                        // 32 chunks per 256-half block
    int lane = g & 31;
    int m16 = blk >> 5, k16 = blk & 31;
    int t = m16 >> 1;
    uint32_t mbits = g_mbt[t];
    int mA = m16 * 16 + ((lane >> 2) & 7);
    int mB = mA + 8;
    bool padA = ((mbits >> (mA & 31)) & 1u) == 0u;
    bool padB = ((mbits >> (mB & 31)) & 1u) == 0u;
    int k0 = k16 * 16 + (lane & 3) * 2;

    const float* vr = vc   + layer * 2 * DIM + DIM;
    const float* br = bias + layer * 2 * DIM + DIM;
    float2 vr0 = *(const float2*)(vr + k0);
    float2 vr8 = *(const float2*)(vr + k0 + 8);
    float2 br0 = *(const float2*)(br + k0);
    float2 br8 = *(const float2*)(br + k0 + 8);

    size_t off = (size_t)blk * 256 + (size_t)lane * 8;
    uint4 cu = *(const uint4*)(g_ch  + off);
    uint4 xu = *(const uint4*)(g_hh  + off);
    uint4 uu = *(const uint4*)(g_u2h + off);
    const __half2* ch = (const __half2*)&cu;
    const __half2* xh = (const __half2*)&xu;
    const __half2* uh = (const __half2*)&uu;

    // element order e=0..7: (reg=e>>1, hb=e&1); pairs are half2 (hb 0,1)
    // e-pair p=0: mA,(k0,k0+1)  p=1: mB,(k0,k0+1)  p=2: mA,(k0+8,k0+9)  p=3: mB,(k0+8,k0+9)
    float vrv[4] = {vr0.x, vr0.y, vr8.x, vr8.y};   // by k index 0,1,8,9
    float brv[4] = {br0.x, br0.y, br8.x, br8.y};
    bool  padp[4] = {padA, padB, padA, padB};

    __half2 res[4];
    #pragma unroll
    for (int p = 0; p < 4; p++) {
        float2 cf = __half22float2(ch[p]);
        float2 xf = __half22float2(xh[p]);
        float2 uf = __half22float2(uh[p]);
        int kk = (p >> 1) * 2;                 // 0 or 2 -> vrv index base
        float z0 = fmaf(vrv[kk],   cf.x, uf.x + brv[kk]);
        float z1 = fmaf(vrv[kk+1], cf.y, uf.y + brv[kk+1]);
        float r0 = rcpf(1.f + ex2f(-L2E * z0));
        float r1 = rcpf(1.f + ex2f(-L2E * z1));
        float h0 = fmaf(r0, cf.x - xf.x, xf.x);
        float h1 = fmaf(r1, cf.y - xf.y, xf.y);
        if (padp[p]) { h0 = 0.f; h1 = 0.f; }
        res[p] = __floats2half2_rn(h0, h1);
    }
    uint4 ro;
    __half2* rh = (__half2*)&ro;
    rh[0] = res[0]; rh[1] = res[1]; rh[2] = res[2]; rh[3] = res[3];
    *(uint4*)(g_hh + off) = ro;
}

// ---------------- launch -----------------------------------------------------
extern "C" void kernel_launch(void* const* d_in, const int* in_sizes, int n_in,
                              void* d_out, int out_size)
{
    const float* x     = (const float*)d_in[0];
    const int*   mask  = (const int*)  d_in[1];
    const float* state = (const float*)d_in[2];
    const float* W     = (const float*)d_in[3];
    const float* vc    = (const float*)d_in[4];
    const float* bias  = (const float*)d_in[5];
    float* out = (float*)d_out;

    cudaFuncSetAttribute(gemm_kernel,
                         cudaFuncAttributeMaxDynamicSharedMemorySize, SMEM_TOTAL);
    cudaFuncSetAttribute(cscan_kernel<false>,
                         cudaFuncAttributeMaxDynamicSharedMemorySize, RSMEM);
    cudaFuncSetAttribute(cscan_kernel<true>,
                         cudaFuncAttributeMaxDynamicSharedMemorySize, RSMEM);

    split_x_kernel<<<BATCH * L_SEQ, 128>>>(x);
    split_w_kernel<<<(NLAY * NTOT * DIM) / 256, 256>>>(W);
    pack_mask_kernel<<<BATCH, 64>>>(mask);
    pack_mask_t_kernel<<<L_SEQ / 128, 128>>>(mask);

    for (int l = 0; l < NLAY; l++) {
        int nt = (l == NLAY - 1) ? 8 : 12;   // last layer: skip u2 tiles
        gemm_kernel<<<(MTOT / MT) * nt, 256, SMEM_TOTAL>>>(l, nt);
        if (l == NLAY - 1) {
            cscan_kernel<true><<<(BATCH * DIM) / 128, 128, RSMEM>>>(state, vc, bias, out, l);
        } else {
            cscan_kernel<false><<<(BATCH * DIM) / 128, 128, RSMEM>>>(state, vc, bias, out, l);
            hupdate_kernel<<<(int)((size_t)MTOT * DIM / 8 / 256), 256>>>(vc, bias, l);
        }
    }
    (void)in_sizes; (void)n_in; (void)out_size;
}